// round 13
// baseline (speedup 1.0000x reference)
#include <cuda_runtime.h>
#include <cuda_bf16.h>
#include <cstdint>

#define N_MAX   50000
#define OUT     128
#define EDIM    64

// ---------------- device scratch ----------------
__device__ __align__(16) float g_W1[128 * 128];
__device__ __align__(16) float g_W2[64 * 128];    // [k][n] fp32
__device__ __align__(16) float g_c[128];
__device__ __align__(16) float g_A[(size_t)N_MAX * OUT];    // x@W1 + c (bias folded)
__device__ __align__(16) float g_agg[(size_t)N_MAX * OUT];
__device__ int g_is64;
__device__ unsigned g_bar;

// ---------------- helpers ----------------
__device__ __forceinline__ uint32_t smem_u32(const void* p) {
    uint32_t a;
    asm("{ .reg .u64 t; cvta.to.shared.u64 t, %1; cvt.u32.u64 %0, t; }" : "=r"(a) : "l"(p));
    return a;
}
#define SW128(off) ((off) ^ (((off) >> 3) & 0x70))

__device__ __forceinline__ void ldsm4(uint32_t& r0, uint32_t& r1, uint32_t& r2,
                                      uint32_t& r3, uint32_t a) {
    asm volatile("ldmatrix.sync.aligned.m8n8.x4.shared.b16 {%0,%1,%2,%3}, [%4];"
                 : "=r"(r0), "=r"(r1), "=r"(r2), "=r"(r3) : "r"(a));
}
__device__ __forceinline__ void mma16816(float* c, const uint32_t* a, uint32_t b0,
                                         uint32_t b1) {
    asm volatile(
        "mma.sync.aligned.m16n8k16.row.col.f32.bf16.bf16.f32 "
        "{%0,%1,%2,%3}, {%4,%5,%6,%7}, {%8,%9}, {%0,%1,%2,%3};"
        : "+f"(c[0]), "+f"(c[1]), "+f"(c[2]), "+f"(c[3])
        : "r"(a[0]), "r"(a[1]), "r"(a[2]), "r"(a[3]), "r"(b0), "r"(b1));
}
__device__ __forceinline__ void split2(const float2 v, uint32_t& h, uint32_t& l) {
    asm("cvt.rn.bf16x2.f32 %0, %1, %2;" : "=r"(h) : "f"(v.y), "f"(v.x));
    const float hx = __uint_as_float(h << 16);
    const float hy = __uint_as_float(h & 0xffff0000u);
    asm("cvt.rn.bf16x2.f32 %0, %1, %2;" : "=r"(l) : "f"(v.y - hy), "f"(v.x - hx));
}
__device__ __forceinline__ float lky(float x) { return (x > 0.f) ? x : 0.01f * x; }

// ---------------- fold weights + detect int64 + reset barrier (fused) ----------------
__global__ void prep_kernel(const float* __restrict__ Wx, const float* __restrict__ bx,
                            const float* __restrict__ We, const float* __restrict__ be,
                            const float* __restrict__ Wm, const float* __restrict__ bm,
                            const int* __restrict__ idx) {
    __shared__ float row[128];
    __shared__ float row2[128];
    const int b = blockIdx.x;
    const int j = threadIdx.x;
    if (b == 193) {
        if (j == 0) {
            int ok = 1;
            for (int i = 1; i < 64; i += 2)
                if (idx[i] != 0) ok = 0;
            g_is64 = ok;
            g_bar = 0u;   // reset grid barrier for this launch/replay
        }
        return;
    }
    if (b < 128) {
        row[j] = Wx[b * 128 + j];
        __syncthreads();
        float s = 0.f;
#pragma unroll 8
        for (int k = 0; k < 128; k++) s = fmaf(row[k], Wm[k * 128 + j], s);
        g_W1[b * 128 + j] = s;
    } else if (b < 192) {
        const int i = b - 128;
        row[j] = We[i * 128 + j];
        __syncthreads();
        float s = 0.f;
#pragma unroll 8
        for (int k = 0; k < 128; k++) s = fmaf(row[k], Wm[(128 + k) * 128 + j], s);
        g_W2[i * 128 + j] = s;
    } else {
        row[j] = bx[j];
        row2[j] = be[j];
        __syncthreads();
        float s = bm[j];
#pragma unroll 8
        for (int k = 0; k < 128; k++) {
            s = fmaf(row[k], Wm[k * 128 + j], s);
            s = fmaf(row2[k], Wm[(128 + k) * 128 + j], s);
        }
        g_c[j] = s;
    }
}

// ---------------- node GEMM: direct-LDG A frags, bf16 mma x3, bias folded ----------------
#define NB_HI     0
#define NB_LO     32768
#define NODE_SMEM 65536

__global__ void __launch_bounds__(256, 2) node_mma_kernel(const float* __restrict__ x,
                                                          int N, int ntiles, int n4) {
    extern __shared__ char smem[];
    const uint32_t sb = smem_u32(smem);
    const int tid = threadIdx.x;
    const int wid = tid >> 5;
    const int lane = tid & 31;

    // fused: zero the aggregation buffer (fire-and-forget STGs overlap GEMM)
    {
        const float4 z = make_float4(0.f, 0.f, 0.f, 0.f);
        const int stride = gridDim.x * blockDim.x;
        for (int i = blockIdx.x * blockDim.x + tid; i < n4; i += stride)
            reinterpret_cast<float4*>(g_agg)[i] = z;
    }

    for (int i = tid; i < 128 * 128; i += 256) {
        const int k = i >> 7, n = i & 127;
        const float v = g_W1[i];
        const __nv_bfloat16 h = __float2bfloat16(v);
        const __nv_bfloat16 l = __float2bfloat16(v - __bfloat162float(h));
        const uint32_t off = (uint32_t)(n * 2 + (k >> 6)) * 128 + (uint32_t)(k & 63) * 2;
        const uint32_t sw = SW128(off);
        *reinterpret_cast<__nv_bfloat16*>(smem + NB_HI + sw) = h;
        *reinterpret_cast<__nv_bfloat16*>(smem + NB_LO + sw) = l;
    }
    __syncthreads();

    const int qd = lane >> 2;
    const int tq = lane & 3;
    const int b_row = ((lane >= 16) ? 8 : 0) + (lane & 7);
    const int b_kb = ((lane >> 3) & 1) * 16;

    for (int tp = blockIdx.x; tp < ntiles; tp += gridDim.x) {
        const int base_r = tp * 128 + wid * 16;

        const int r_lo = min(base_r + qd, N - 1);
        const int r_hi = min(base_r + qd + 8, N - 1);
        const float* plo = x + (size_t)r_lo * 128 + 2 * tq;
        const float* phi = x + (size_t)r_hi * 128 + 2 * tq;
        uint32_t ah[8][4], al[8][4];
#pragma unroll
        for (int ks = 0; ks < 8; ks++) {
            const float2 v00 = __ldg(reinterpret_cast<const float2*>(plo + ks * 16));
            const float2 v10 = __ldg(reinterpret_cast<const float2*>(phi + ks * 16));
            const float2 v01 = __ldg(reinterpret_cast<const float2*>(plo + ks * 16 + 8));
            const float2 v11 = __ldg(reinterpret_cast<const float2*>(phi + ks * 16 + 8));
            split2(v00, ah[ks][0], al[ks][0]);
            split2(v10, ah[ks][1], al[ks][1]);
            split2(v01, ah[ks][2], al[ks][2]);
            split2(v11, ah[ks][3], al[ks][3]);
        }

#pragma unroll
        for (int jp = 0; jp < 4; jp++) {
            const int j0 = jp * 2, j1 = jp * 2 + 1;
            float p0[4] = {0.f, 0.f, 0.f, 0.f}, p1[4] = {0.f, 0.f, 0.f, 0.f};
            float q0[4] = {0.f, 0.f, 0.f, 0.f}, q1[4] = {0.f, 0.f, 0.f, 0.f};
#pragma unroll
            for (int ks = 0; ks < 8; ks++) {
                const uint32_t base_off = (uint32_t)((ks >> 2) * 128 +
                                                     (ks & 3) * 32 + b_kb);
                const uint32_t sw0 = SW128((uint32_t)((16 * j0 + b_row) * 256) + base_off);
                const uint32_t sw1 = SW128((uint32_t)((16 * j1 + b_row) * 256) + base_off);
                uint32_t bh0, bh1, bh2, bh3, bl0, bl1, bl2, bl3;
                uint32_t ch0, ch1, ch2, ch3, cl0, cl1, cl2, cl3;
                ldsm4(bh0, bh1, bh2, bh3, sb + NB_HI + sw0);
                ldsm4(bl0, bl1, bl2, bl3, sb + NB_LO + sw0);
                ldsm4(ch0, ch1, ch2, ch3, sb + NB_HI + sw1);
                ldsm4(cl0, cl1, cl2, cl3, sb + NB_LO + sw1);
                mma16816(p0, ah[ks], bh0, bh1);
                mma16816(p1, ah[ks], bh2, bh3);
                mma16816(q0, ah[ks], ch0, ch1);
                mma16816(q1, ah[ks], ch2, ch3);
                mma16816(p0, ah[ks], bl0, bl1);
                mma16816(p1, ah[ks], bl2, bl3);
                mma16816(q0, ah[ks], cl0, cl1);
                mma16816(q1, ah[ks], cl2, cl3);
                mma16816(p0, al[ks], bh0, bh1);
                mma16816(p1, al[ks], bh2, bh3);
                mma16816(q0, al[ks], ch0, ch1);
                mma16816(q1, al[ks], ch2, ch3);
            }
            const int r0 = base_r + (lane >> 2);
            const int c0 = 2 * (lane & 3);
            const float2 cj0a = __ldg(reinterpret_cast<const float2*>(g_c + j0 * 16 + c0));
            const float2 cj0b = __ldg(reinterpret_cast<const float2*>(g_c + j0 * 16 + c0 + 8));
            const float2 cj1a = __ldg(reinterpret_cast<const float2*>(g_c + j1 * 16 + c0));
            const float2 cj1b = __ldg(reinterpret_cast<const float2*>(g_c + j1 * 16 + c0 + 8));
            if (r0 < N) {
                float* p = &g_A[(size_t)r0 * 128];
                *reinterpret_cast<float2*>(p + j0 * 16 + c0) =
                    make_float2(p0[0] + cj0a.x, p0[1] + cj0a.y);
                *reinterpret_cast<float2*>(p + j0 * 16 + c0 + 8) =
                    make_float2(p1[0] + cj0b.x, p1[1] + cj0b.y);
                *reinterpret_cast<float2*>(p + j1 * 16 + c0) =
                    make_float2(q0[0] + cj1a.x, q0[1] + cj1a.y);
                *reinterpret_cast<float2*>(p + j1 * 16 + c0 + 8) =
                    make_float2(q1[0] + cj1b.x, q1[1] + cj1b.y);
            }
            if (r0 + 8 < N) {
                float* p = &g_A[(size_t)(r0 + 8) * 128];
                *reinterpret_cast<float2*>(p + j0 * 16 + c0) =
                    make_float2(p0[2] + cj0a.x, p0[3] + cj0a.y);
                *reinterpret_cast<float2*>(p + j0 * 16 + c0 + 8) =
                    make_float2(p1[2] + cj0b.x, p1[3] + cj0b.y);
                *reinterpret_cast<float2*>(p + j1 * 16 + c0) =
                    make_float2(q0[2] + cj1a.x, q0[3] + cj1a.y);
                *reinterpret_cast<float2*>(p + j1 * 16 + c0 + 8) =
                    make_float2(q1[2] + cj1b.x, q1[3] + cj1b.y);
            }
        }
    }
}

// ---------------- edge kernel: R9 structure + fused sigmoid epilogue (grid barrier) ----------------
// SMEM: B_hi 16KB | B_lo 16KB | 8 warp D regions [16 x 136 fp32]
#define B_HI_OFF  0
#define B_LO_OFF  16384
#define WARP_D    32768
#define DSTRIDE   136
#define WD_SZ     (16 * DSTRIDE * 4)
#define EDGE_SMEM (32768 + 8 * WD_SZ)

__global__ void __launch_bounds__(256, 2) edge_mma_kernel(const float* __restrict__ ea,
                                                          const int* __restrict__ idx,
                                                          int E, int ngroups,
                                                          float* __restrict__ out,
                                                          const float* __restrict__ beta,
                                                          int n4) {
    extern __shared__ char smem[];
    const uint32_t sb = smem_u32(smem);
    const int tid = threadIdx.x;
    const int wid = tid >> 5;
    const int lane = tid & 31;
    const int is64 = g_is64;

    // build B tiles (hi/lo split of W2^T)
    for (int i = tid; i < 64 * 128; i += 256) {
        const int k = i >> 7, n = i & 127;
        const float v = g_W2[i];
        const __nv_bfloat16 h = __float2bfloat16(v);
        const __nv_bfloat16 l = __float2bfloat16(v - __bfloat162float(h));
        const uint32_t off = (uint32_t)n * 128 + (uint32_t)k * 2;
        const uint32_t sw = SW128(off);
        *reinterpret_cast<__nv_bfloat16*>(smem + B_HI_OFF + sw) = h;
        *reinterpret_cast<__nv_bfloat16*>(smem + B_LO_OFF + sw) = l;
    }
    __syncthreads();

    float* dbuf = reinterpret_cast<float*>(smem + WARP_D + wid * WD_SZ);

    const int qd = lane >> 2;
    const int tq = lane & 3;
    const int b_row = ((lane >= 16) ? 8 : 0) + (lane & 7);
    const int b_kb = ((lane >> 3) & 1) * 16;

    const int gw = blockIdx.x * 8 + wid;
    const int nwarps = gridDim.x * 8;

    for (int g = gw; g < ngroups; g += nwarps) {
        const long long base_e = (long long)g * 16;

        // ---- A fragments directly from global (hi/lo split in regs) ----
        const long long e_lo = min(base_e + qd, (long long)E - 1);
        const long long e_hi = min(base_e + qd + 8, (long long)E - 1);
        const float* plo = ea + e_lo * 64 + 2 * tq;
        const float* phi = ea + e_hi * 64 + 2 * tq;
        uint32_t ah[4][4], al[4][4];
#pragma unroll
        for (int ks = 0; ks < 4; ks++) {
            const float2 v00 = __ldg(reinterpret_cast<const float2*>(plo + ks * 16));
            const float2 v10 = __ldg(reinterpret_cast<const float2*>(phi + ks * 16));
            const float2 v01 = __ldg(reinterpret_cast<const float2*>(plo + ks * 16 + 8));
            const float2 v11 = __ldg(reinterpret_cast<const float2*>(phi + ks * 16 + 8));
            split2(v00, ah[ks][0], al[ks][0]);
            split2(v10, ah[ks][1], al[ks][1]);
            split2(v01, ah[ks][2], al[ks][2]);
            split2(v11, ah[ks][3], al[ks][3]);
        }

        // ---- edge indices: lane t (<16) holds edge base_e + t ----
        int sidx = 0, didx = 0;
        {
            const long long e = base_e + lane;
            if (lane < 16 && e < E) {
                sidx = idx[is64 ? 2 * e : e];
                didx = idx[is64 ? 2 * (e + E) : (e + E)];
            }
        }

        // ---- compute: 8 n-pairs; SPLIT acc chains (hi-chain + cross-chain) ----
#pragma unroll
        for (int j = 0; j < 8; j++) {
            float a0h[4] = {0.f, 0.f, 0.f, 0.f}, a0x[4] = {0.f, 0.f, 0.f, 0.f};
            float a1h[4] = {0.f, 0.f, 0.f, 0.f}, a1x[4] = {0.f, 0.f, 0.f, 0.f};
#pragma unroll
            for (int ks = 0; ks < 4; ks++) {
                const uint32_t boff =
                    (uint32_t)((16 * j + b_row) * 128 + ks * 32 + b_kb);
                const uint32_t sw = SW128(boff);
                uint32_t bh0, bh1, bh2, bh3, bl0, bl1, bl2, bl3;
                ldsm4(bh0, bh1, bh2, bh3, sb + B_HI_OFF + sw);
                ldsm4(bl0, bl1, bl2, bl3, sb + B_LO_OFF + sw);
                mma16816(a0h, ah[ks], bh0, bh1);      // hi*hi chain (depth 4)
                mma16816(a1h, ah[ks], bh2, bh3);
                mma16816(a0x, ah[ks], bl0, bl1);      // cross chain (depth 8)
                mma16816(a1x, ah[ks], bl2, bl3);
                mma16816(a0x, al[ks], bh0, bh1);
                mma16816(a1x, al[ks], bh2, bh3);
            }
            const int r0 = lane >> 2;
            const int c0 = j * 16 + 2 * (lane & 3);
            *reinterpret_cast<float2*>(dbuf + r0 * DSTRIDE + c0) =
                make_float2(a0h[0] + a0x[0], a0h[1] + a0x[1]);
            *reinterpret_cast<float2*>(dbuf + (r0 + 8) * DSTRIDE + c0) =
                make_float2(a0h[2] + a0x[2], a0h[3] + a0x[3]);
            *reinterpret_cast<float2*>(dbuf + r0 * DSTRIDE + c0 + 8) =
                make_float2(a1h[0] + a1x[0], a1h[1] + a1x[1]);
            *reinterpret_cast<float2*>(dbuf + (r0 + 8) * DSTRIDE + c0 + 8) =
                make_float2(a1h[2] + a1x[2], a1h[3] + a1x[3]);
        }
        __syncwarp();

        // ---- epilogue: coalesced gather (pipelined depth 2) + leaky + v4 RED ----
        const int cnt = (int)min((long long)16, (long long)E - base_e);
        float4 gbuf[2];
        int dd[2];
        {
            const int s0 = __shfl_sync(0xffffffffu, sidx, 0);
            dd[0] = __shfl_sync(0xffffffffu, didx, 0);
            gbuf[0] = __ldg(reinterpret_cast<const float4*>(
                &g_A[(size_t)s0 * 128 + lane * 4]));
            if (cnt > 1) {
                const int s1 = __shfl_sync(0xffffffffu, sidx, 1);
                dd[1] = __shfl_sync(0xffffffffu, didx, 1);
                gbuf[1] = __ldg(reinterpret_cast<const float4*>(
                    &g_A[(size_t)s1 * 128 + lane * 4]));
            }
        }
        if (cnt == 16) {
            // fast path: no bounds checks
#pragma unroll 4
            for (int t = 0; t < 16; t++) {
                const float4 av = gbuf[t & 1];
                const int d = dd[t & 1];
                if (t + 2 < 16) {
                    const int sn = __shfl_sync(0xffffffffu, sidx, t + 2);
                    dd[t & 1] = __shfl_sync(0xffffffffu, didx, t + 2);
                    gbuf[t & 1] = __ldg(reinterpret_cast<const float4*>(
                        &g_A[(size_t)sn * 128 + lane * 4]));
                }
                const float4 dv =
                    *reinterpret_cast<const float4*>(dbuf + t * DSTRIDE + lane * 4);
                const float o0 = lky(dv.x + av.x);
                const float o1 = lky(dv.y + av.y);
                const float o2 = lky(dv.z + av.z);
                const float o3 = lky(dv.w + av.w);
                asm volatile("red.global.add.v4.f32 [%0], {%1, %2, %3, %4};" ::
                                 "l"(&g_agg[(size_t)d * 128 + lane * 4]),
                                 "f"(o0), "f"(o1), "f"(o2), "f"(o3)
                             : "memory");
            }
        } else {
            for (int t = 0; t < cnt; t++) {
                const float4 av = gbuf[t & 1];
                const int d = dd[t & 1];
                if (t + 2 < cnt) {
                    const int sn = __shfl_sync(0xffffffffu, sidx, t + 2);
                    dd[t & 1] = __shfl_sync(0xffffffffu, didx, t + 2);
                    gbuf[t & 1] = __ldg(reinterpret_cast<const float4*>(
                        &g_A[(size_t)sn * 128 + lane * 4]));
                }
                const float4 dv =
                    *reinterpret_cast<const float4*>(dbuf + t * DSTRIDE + lane * 4);
                const float o0 = lky(dv.x + av.x);
                const float o1 = lky(dv.y + av.y);
                const float o2 = lky(dv.z + av.z);
                const float o3 = lky(dv.w + av.w);
                asm volatile("red.global.add.v4.f32 [%0], {%1, %2, %3, %4};" ::
                                 "l"(&g_agg[(size_t)d * 128 + lane * 4]),
                                 "f"(o0), "f"(o1), "f"(o2), "f"(o3)
                             : "memory");
            }
        }
        __syncwarp();  // D region reused next group
    }

    // ---- grid-wide barrier: all REDs done, then fused sigmoid epilogue ----
    __threadfence();
    __syncthreads();
    if (tid == 0) {
        atomicAdd(&g_bar, 1u);
        while (*reinterpret_cast<volatile unsigned*>(&g_bar) < (unsigned)gridDim.x) { }
    }
    __syncthreads();
    __threadfence();

    {
        float b = beta[0];
        b = (b > 0.f) ? b : 0.f;
        const int stride = gridDim.x * blockDim.x;
        for (int i = blockIdx.x * blockDim.x + tid; i < n4; i += stride) {
            float4 v = reinterpret_cast<const float4*>(g_agg)[i];
            v.x = b / (1.f + __expf(-v.x));
            v.y = b / (1.f + __expf(-v.y));
            v.z = b / (1.f + __expf(-v.z));
            v.w = b / (1.f + __expf(-v.w));
            reinterpret_cast<float4*>(out)[i] = v;
        }
    }
}

// ---------------- launch ----------------
extern "C" void kernel_launch(void* const* d_in, const int* in_sizes, int n_in,
                              void* d_out, int out_size) {
    const float* x    = (const float*)d_in[0];
    const int*   idx  = (const int*)d_in[1];
    const float* ea   = (const float*)d_in[2];
    const float* Wx   = (const float*)d_in[3];
    const float* bx   = (const float*)d_in[4];
    const float* We   = (const float*)d_in[5];
    const float* be   = (const float*)d_in[6];
    const float* Wm   = (const float*)d_in[7];
    const float* bm   = (const float*)d_in[8];
    const float* beta = (const float*)d_in[9];

    const int N = in_sizes[0] / 128;
    const int E = in_sizes[2] / 64;
    const int n_tiles_node = (N + 127) / 128;
    const int ngroups = (E + 15) / 16;
    const int n4 = N * OUT / 4;

    prep_kernel<<<194, 128>>>(Wx, bx, We, be, Wm, bm, idx);

    cudaFuncSetAttribute(node_mma_kernel, cudaFuncAttributeMaxDynamicSharedMemorySize,
                         NODE_SMEM);
    node_mma_kernel<<<n_tiles_node, 256, NODE_SMEM>>>(x, N, n_tiles_node, n4);

    cudaFuncSetAttribute(edge_mma_kernel, cudaFuncAttributeMaxDynamicSharedMemorySize,
                         EDGE_SMEM);
    edge_mma_kernel<<<148 * 2, 256, EDGE_SMEM>>>(ea, idx, E, ngroups,
                                                 (float*)d_out, beta, n4);
}

// round 14
// speedup vs baseline: 1.4308x; 1.4308x over previous
#include <cuda_runtime.h>
#include <cuda_bf16.h>
#include <cstdint>

#define N_MAX   50000
#define OUT     128
#define EDIM    64

// ---------------- device scratch ----------------
__device__ __align__(16) float g_W1[128 * 128];
__device__ __align__(16) float g_W2[64 * 128];    // [k][n] fp32
__device__ __align__(16) float g_c[128];
__device__ __align__(16) float g_A[(size_t)N_MAX * OUT];    // x@W1 + c (bias folded)
__device__ __align__(16) float g_agg[(size_t)N_MAX * OUT];
__device__ int g_is64;

// ---------------- helpers ----------------
__device__ __forceinline__ uint32_t smem_u32(const void* p) {
    uint32_t a;
    asm("{ .reg .u64 t; cvta.to.shared.u64 t, %1; cvt.u32.u64 %0, t; }" : "=r"(a) : "l"(p));
    return a;
}
#define SW128(off) ((off) ^ (((off) >> 3) & 0x70))

__device__ __forceinline__ void ldsm4(uint32_t& r0, uint32_t& r1, uint32_t& r2,
                                      uint32_t& r3, uint32_t a) {
    asm volatile("ldmatrix.sync.aligned.m8n8.x4.shared.b16 {%0,%1,%2,%3}, [%4];"
                 : "=r"(r0), "=r"(r1), "=r"(r2), "=r"(r3) : "r"(a));
}
__device__ __forceinline__ void mma16816(float* c, const uint32_t* a, uint32_t b0,
                                         uint32_t b1) {
    asm volatile(
        "mma.sync.aligned.m16n8k16.row.col.f32.bf16.bf16.f32 "
        "{%0,%1,%2,%3}, {%4,%5,%6,%7}, {%8,%9}, {%0,%1,%2,%3};"
        : "+f"(c[0]), "+f"(c[1]), "+f"(c[2]), "+f"(c[3])
        : "r"(a[0]), "r"(a[1]), "r"(a[2]), "r"(a[3]), "r"(b0), "r"(b1));
}
__device__ __forceinline__ void split2(const float2 v, uint32_t& h, uint32_t& l) {
    asm("cvt.rn.bf16x2.f32 %0, %1, %2;" : "=r"(h) : "f"(v.y), "f"(v.x));
    const float hx = __uint_as_float(h << 16);
    const float hy = __uint_as_float(h & 0xffff0000u);
    asm("cvt.rn.bf16x2.f32 %0, %1, %2;" : "=r"(l) : "f"(v.y - hy), "f"(v.x - hx));
}
__device__ __forceinline__ float lky(float x) { return (x > 0.f) ? x : 0.01f * x; }

// ---------------- fold weights + detect int64 (fused); 4-way k-split ILP ----------------
__global__ void prep_kernel(const float* __restrict__ Wx, const float* __restrict__ bx,
                            const float* __restrict__ We, const float* __restrict__ be,
                            const float* __restrict__ Wm, const float* __restrict__ bm,
                            const int* __restrict__ idx) {
    __shared__ float row[128];
    __shared__ float row2[128];
    const int b = blockIdx.x;
    const int j = threadIdx.x;
    if (b == 193) {
        if (j == 0) {
            int ok = 1;
            for (int i = 1; i < 64; i += 2)
                if (idx[i] != 0) ok = 0;
            g_is64 = ok;
        }
        return;
    }
    if (b < 128) {
        row[j] = Wx[b * 128 + j];
        __syncthreads();
        float s0 = 0.f, s1 = 0.f, s2 = 0.f, s3 = 0.f;
#pragma unroll 8
        for (int k = 0; k < 32; k++) {
            s0 = fmaf(row[k],      __ldg(&Wm[k * 128 + j]), s0);
            s1 = fmaf(row[k + 32], __ldg(&Wm[(k + 32) * 128 + j]), s1);
            s2 = fmaf(row[k + 64], __ldg(&Wm[(k + 64) * 128 + j]), s2);
            s3 = fmaf(row[k + 96], __ldg(&Wm[(k + 96) * 128 + j]), s3);
        }
        g_W1[b * 128 + j] = (s0 + s1) + (s2 + s3);
    } else if (b < 192) {
        const int i = b - 128;
        row[j] = We[i * 128 + j];
        __syncthreads();
        float s0 = 0.f, s1 = 0.f, s2 = 0.f, s3 = 0.f;
#pragma unroll 8
        for (int k = 0; k < 32; k++) {
            s0 = fmaf(row[k],      __ldg(&Wm[(128 + k) * 128 + j]), s0);
            s1 = fmaf(row[k + 32], __ldg(&Wm[(160 + k) * 128 + j]), s1);
            s2 = fmaf(row[k + 64], __ldg(&Wm[(192 + k) * 128 + j]), s2);
            s3 = fmaf(row[k + 96], __ldg(&Wm[(224 + k) * 128 + j]), s3);
        }
        g_W2[i * 128 + j] = (s0 + s1) + (s2 + s3);
    } else {
        row[j] = bx[j];
        row2[j] = be[j];
        __syncthreads();
        float s0 = 0.f, s1 = 0.f, s2 = 0.f, s3 = 0.f;
#pragma unroll 8
        for (int k = 0; k < 64; k++) {
            s0 = fmaf(row[k],       __ldg(&Wm[k * 128 + j]), s0);
            s1 = fmaf(row[k + 64],  __ldg(&Wm[(k + 64) * 128 + j]), s1);
            s2 = fmaf(row2[k],      __ldg(&Wm[(128 + k) * 128 + j]), s2);
            s3 = fmaf(row2[k + 64], __ldg(&Wm[(192 + k) * 128 + j]), s3);
        }
        g_c[j] = bm[j] + (s0 + s1) + (s2 + s3);
    }
}

// ---------------- node GEMM: direct-LDG A frags, bf16 mma x3, bias folded ----------------
#define NB_HI     0
#define NB_LO     32768
#define NODE_SMEM 65536

__global__ void __launch_bounds__(256, 2) node_mma_kernel(const float* __restrict__ x,
                                                          int N, int ntiles, int n4) {
    extern __shared__ char smem[];
    const uint32_t sb = smem_u32(smem);
    const int tid = threadIdx.x;
    const int wid = tid >> 5;
    const int lane = tid & 31;

    // fused: zero the aggregation buffer
    {
        const float4 z = make_float4(0.f, 0.f, 0.f, 0.f);
        const int stride = gridDim.x * blockDim.x;
        for (int i = blockIdx.x * blockDim.x + tid; i < n4; i += stride)
            reinterpret_cast<float4*>(g_agg)[i] = z;
    }

    for (int i = tid; i < 128 * 128; i += 256) {
        const int k = i >> 7, n = i & 127;
        const float v = g_W1[i];
        const __nv_bfloat16 h = __float2bfloat16(v);
        const __nv_bfloat16 l = __float2bfloat16(v - __bfloat162float(h));
        const uint32_t off = (uint32_t)(n * 2 + (k >> 6)) * 128 + (uint32_t)(k & 63) * 2;
        const uint32_t sw = SW128(off);
        *reinterpret_cast<__nv_bfloat16*>(smem + NB_HI + sw) = h;
        *reinterpret_cast<__nv_bfloat16*>(smem + NB_LO + sw) = l;
    }
    __syncthreads();

    const int qd = lane >> 2;
    const int tq = lane & 3;
    const int b_row = ((lane >= 16) ? 8 : 0) + (lane & 7);
    const int b_kb = ((lane >> 3) & 1) * 16;

    for (int tp = blockIdx.x; tp < ntiles; tp += gridDim.x) {
        const int base_r = tp * 128 + wid * 16;

        const int r_lo = min(base_r + qd, N - 1);
        const int r_hi = min(base_r + qd + 8, N - 1);
        const float* plo = x + (size_t)r_lo * 128 + 2 * tq;
        const float* phi = x + (size_t)r_hi * 128 + 2 * tq;
        uint32_t ah[8][4], al[8][4];
#pragma unroll
        for (int ks = 0; ks < 8; ks++) {
            const float2 v00 = __ldg(reinterpret_cast<const float2*>(plo + ks * 16));
            const float2 v10 = __ldg(reinterpret_cast<const float2*>(phi + ks * 16));
            const float2 v01 = __ldg(reinterpret_cast<const float2*>(plo + ks * 16 + 8));
            const float2 v11 = __ldg(reinterpret_cast<const float2*>(phi + ks * 16 + 8));
            split2(v00, ah[ks][0], al[ks][0]);
            split2(v10, ah[ks][1], al[ks][1]);
            split2(v01, ah[ks][2], al[ks][2]);
            split2(v11, ah[ks][3], al[ks][3]);
        }

#pragma unroll
        for (int jp = 0; jp < 4; jp++) {
            const int j0 = jp * 2, j1 = jp * 2 + 1;
            float p0[4] = {0.f, 0.f, 0.f, 0.f}, p1[4] = {0.f, 0.f, 0.f, 0.f};
            float q0[4] = {0.f, 0.f, 0.f, 0.f}, q1[4] = {0.f, 0.f, 0.f, 0.f};
#pragma unroll
            for (int ks = 0; ks < 8; ks++) {
                const uint32_t base_off = (uint32_t)((ks >> 2) * 128 +
                                                     (ks & 3) * 32 + b_kb);
                const uint32_t sw0 = SW128((uint32_t)((16 * j0 + b_row) * 256) + base_off);
                const uint32_t sw1 = SW128((uint32_t)((16 * j1 + b_row) * 256) + base_off);
                uint32_t bh0, bh1, bh2, bh3, bl0, bl1, bl2, bl3;
                uint32_t ch0, ch1, ch2, ch3, cl0, cl1, cl2, cl3;
                ldsm4(bh0, bh1, bh2, bh3, sb + NB_HI + sw0);
                ldsm4(bl0, bl1, bl2, bl3, sb + NB_LO + sw0);
                ldsm4(ch0, ch1, ch2, ch3, sb + NB_HI + sw1);
                ldsm4(cl0, cl1, cl2, cl3, sb + NB_LO + sw1);
                mma16816(p0, ah[ks], bh0, bh1);
                mma16816(p1, ah[ks], bh2, bh3);
                mma16816(q0, ah[ks], ch0, ch1);
                mma16816(q1, ah[ks], ch2, ch3);
                mma16816(p0, ah[ks], bl0, bl1);
                mma16816(p1, ah[ks], bl2, bl3);
                mma16816(q0, ah[ks], cl0, cl1);
                mma16816(q1, ah[ks], cl2, cl3);
                mma16816(p0, al[ks], bh0, bh1);
                mma16816(p1, al[ks], bh2, bh3);
                mma16816(q0, al[ks], ch0, ch1);
                mma16816(q1, al[ks], ch2, ch3);
            }
            const int r0 = base_r + (lane >> 2);
            const int c0 = 2 * (lane & 3);
            const float2 cj0a = __ldg(reinterpret_cast<const float2*>(g_c + j0 * 16 + c0));
            const float2 cj0b = __ldg(reinterpret_cast<const float2*>(g_c + j0 * 16 + c0 + 8));
            const float2 cj1a = __ldg(reinterpret_cast<const float2*>(g_c + j1 * 16 + c0));
            const float2 cj1b = __ldg(reinterpret_cast<const float2*>(g_c + j1 * 16 + c0 + 8));
            if (r0 < N) {
                float* p = &g_A[(size_t)r0 * 128];
                *reinterpret_cast<float2*>(p + j0 * 16 + c0) =
                    make_float2(p0[0] + cj0a.x, p0[1] + cj0a.y);
                *reinterpret_cast<float2*>(p + j0 * 16 + c0 + 8) =
                    make_float2(p1[0] + cj0b.x, p1[1] + cj0b.y);
                *reinterpret_cast<float2*>(p + j1 * 16 + c0) =
                    make_float2(q0[0] + cj1a.x, q0[1] + cj1a.y);
                *reinterpret_cast<float2*>(p + j1 * 16 + c0 + 8) =
                    make_float2(q1[0] + cj1b.x, q1[1] + cj1b.y);
            }
            if (r0 + 8 < N) {
                float* p = &g_A[(size_t)(r0 + 8) * 128];
                *reinterpret_cast<float2*>(p + j0 * 16 + c0) =
                    make_float2(p0[2] + cj0a.x, p0[3] + cj0a.y);
                *reinterpret_cast<float2*>(p + j0 * 16 + c0 + 8) =
                    make_float2(p1[2] + cj0b.x, p1[3] + cj0b.y);
                *reinterpret_cast<float2*>(p + j1 * 16 + c0) =
                    make_float2(q0[2] + cj1a.x, q0[3] + cj1a.y);
                *reinterpret_cast<float2*>(p + j1 * 16 + c0 + 8) =
                    make_float2(q1[2] + cj1b.x, q1[3] + cj1b.y);
            }
        }
    }
}

// ---------------- edge kernel: R9/R12 structure (depth-2 gather pipeline, v4 RED) ----------------
// SMEM: B_hi 16KB | B_lo 16KB | 8 warp D regions [16 x 136 fp32]
#define B_HI_OFF  0
#define B_LO_OFF  16384
#define WARP_D    32768
#define DSTRIDE   136
#define WD_SZ     (16 * DSTRIDE * 4)
#define EDGE_SMEM (32768 + 8 * WD_SZ)

__global__ void __launch_bounds__(256, 2) edge_mma_kernel(const float* __restrict__ ea,
                                                          const int* __restrict__ idx,
                                                          int E, int ngroups) {
    extern __shared__ char smem[];
    const uint32_t sb = smem_u32(smem);
    const int tid = threadIdx.x;
    const int wid = tid >> 5;
    const int lane = tid & 31;
    const int is64 = g_is64;

    // build B tiles (hi/lo split of W2^T)
    for (int i = tid; i < 64 * 128; i += 256) {
        const int k = i >> 7, n = i & 127;
        const float v = g_W2[i];
        const __nv_bfloat16 h = __float2bfloat16(v);
        const __nv_bfloat16 l = __float2bfloat16(v - __bfloat162float(h));
        const uint32_t off = (uint32_t)n * 128 + (uint32_t)k * 2;
        const uint32_t sw = SW128(off);
        *reinterpret_cast<__nv_bfloat16*>(smem + B_HI_OFF + sw) = h;
        *reinterpret_cast<__nv_bfloat16*>(smem + B_LO_OFF + sw) = l;
    }
    __syncthreads();

    float* dbuf = reinterpret_cast<float*>(smem + WARP_D + wid * WD_SZ);

    const int qd = lane >> 2;
    const int tq = lane & 3;
    const int b_row = ((lane >= 16) ? 8 : 0) + (lane & 7);
    const int b_kb = ((lane >> 3) & 1) * 16;

    const int gw = blockIdx.x * 8 + wid;
    const int nwarps = gridDim.x * 8;

    for (int g = gw; g < ngroups; g += nwarps) {
        const long long base_e = (long long)g * 16;

        // ---- A fragments directly from global (hi/lo split in regs) ----
        const long long e_lo = min(base_e + qd, (long long)E - 1);
        const long long e_hi = min(base_e + qd + 8, (long long)E - 1);
        const float* plo = ea + e_lo * 64 + 2 * tq;
        const float* phi = ea + e_hi * 64 + 2 * tq;
        uint32_t ah[4][4], al[4][4];
#pragma unroll
        for (int ks = 0; ks < 4; ks++) {
            const float2 v00 = __ldg(reinterpret_cast<const float2*>(plo + ks * 16));
            const float2 v10 = __ldg(reinterpret_cast<const float2*>(phi + ks * 16));
            const float2 v01 = __ldg(reinterpret_cast<const float2*>(plo + ks * 16 + 8));
            const float2 v11 = __ldg(reinterpret_cast<const float2*>(phi + ks * 16 + 8));
            split2(v00, ah[ks][0], al[ks][0]);
            split2(v10, ah[ks][1], al[ks][1]);
            split2(v01, ah[ks][2], al[ks][2]);
            split2(v11, ah[ks][3], al[ks][3]);
        }

        // ---- edge indices: lane t (<16) holds edge base_e + t ----
        int sidx = 0, didx = 0;
        {
            const long long e = base_e + lane;
            if (lane < 16 && e < E) {
                sidx = idx[is64 ? 2 * e : e];
                didx = idx[is64 ? 2 * (e + E) : (e + E)];
            }
        }

        // ---- compute: 8 n-pairs; SPLIT acc chains (hi-chain + cross-chain) ----
#pragma unroll
        for (int j = 0; j < 8; j++) {
            float a0h[4] = {0.f, 0.f, 0.f, 0.f}, a0x[4] = {0.f, 0.f, 0.f, 0.f};
            float a1h[4] = {0.f, 0.f, 0.f, 0.f}, a1x[4] = {0.f, 0.f, 0.f, 0.f};
#pragma unroll
            for (int ks = 0; ks < 4; ks++) {
                const uint32_t boff =
                    (uint32_t)((16 * j + b_row) * 128 + ks * 32 + b_kb);
                const uint32_t sw = SW128(boff);
                uint32_t bh0, bh1, bh2, bh3, bl0, bl1, bl2, bl3;
                ldsm4(bh0, bh1, bh2, bh3, sb + B_HI_OFF + sw);
                ldsm4(bl0, bl1, bl2, bl3, sb + B_LO_OFF + sw);
                mma16816(a0h, ah[ks], bh0, bh1);      // hi*hi chain (depth 4)
                mma16816(a1h, ah[ks], bh2, bh3);
                mma16816(a0x, ah[ks], bl0, bl1);      // cross chain (depth 8)
                mma16816(a1x, ah[ks], bl2, bl3);
                mma16816(a0x, al[ks], bh0, bh1);
                mma16816(a1x, al[ks], bh2, bh3);
            }
            const int r0 = lane >> 2;
            const int c0 = j * 16 + 2 * (lane & 3);
            *reinterpret_cast<float2*>(dbuf + r0 * DSTRIDE + c0) =
                make_float2(a0h[0] + a0x[0], a0h[1] + a0x[1]);
            *reinterpret_cast<float2*>(dbuf + (r0 + 8) * DSTRIDE + c0) =
                make_float2(a0h[2] + a0x[2], a0h[3] + a0x[3]);
            *reinterpret_cast<float2*>(dbuf + r0 * DSTRIDE + c0 + 8) =
                make_float2(a1h[0] + a1x[0], a1h[1] + a1x[1]);
            *reinterpret_cast<float2*>(dbuf + (r0 + 8) * DSTRIDE + c0 + 8) =
                make_float2(a1h[2] + a1x[2], a1h[3] + a1x[3]);
        }
        __syncwarp();

        // ---- epilogue: coalesced gather (pipelined depth 2) + leaky + v4 RED ----
        const int cnt = (int)min((long long)16, (long long)E - base_e);
        float4 gbuf[2];
        int dd[2];
        {
            const int s0 = __shfl_sync(0xffffffffu, sidx, 0);
            dd[0] = __shfl_sync(0xffffffffu, didx, 0);
            gbuf[0] = __ldg(reinterpret_cast<const float4*>(
                &g_A[(size_t)s0 * 128 + lane * 4]));
            if (cnt > 1) {
                const int s1 = __shfl_sync(0xffffffffu, sidx, 1);
                dd[1] = __shfl_sync(0xffffffffu, didx, 1);
                gbuf[1] = __ldg(reinterpret_cast<const float4*>(
                    &g_A[(size_t)s1 * 128 + lane * 4]));
            }
        }
#pragma unroll 4
        for (int t = 0; t < 16; t++) {
            if (t >= cnt) break;
            const float4 av = gbuf[t & 1];
            const int d = dd[t & 1];
            // prefetch t+2
            if (t + 2 < cnt) {
                const int sn = __shfl_sync(0xffffffffu, sidx, t + 2);
                dd[t & 1] = __shfl_sync(0xffffffffu, didx, t + 2);
                gbuf[t & 1] = __ldg(reinterpret_cast<const float4*>(
                    &g_A[(size_t)sn * 128 + lane * 4]));
            }
            const float4 dv =
                *reinterpret_cast<const float4*>(dbuf + t * DSTRIDE + lane * 4);
            const float o0 = lky(dv.x + av.x);
            const float o1 = lky(dv.y + av.y);
            const float o2 = lky(dv.z + av.z);
            const float o3 = lky(dv.w + av.w);
            asm volatile("red.global.add.v4.f32 [%0], {%1, %2, %3, %4};" ::
                             "l"(&g_agg[(size_t)d * 128 + lane * 4]),
                             "f"(o0), "f"(o1), "f"(o2), "f"(o3)
                         : "memory");
        }
        __syncwarp();  // D region reused next group
    }
}

// ---------------- epilogue: out = sigmoid(agg) * relu(beta) ----------------
__global__ void final_kernel(float* __restrict__ out, const float* __restrict__ beta,
                             int n4) {
    float b = beta[0];
    b = (b > 0.f) ? b : 0.f;
    int i = blockIdx.x * blockDim.x + threadIdx.x;
    const int stride = gridDim.x * blockDim.x;
    for (; i < n4; i += stride) {
        float4 v = reinterpret_cast<const float4*>(g_agg)[i];
        v.x = b / (1.f + __expf(-v.x));
        v.y = b / (1.f + __expf(-v.y));
        v.z = b / (1.f + __expf(-v.z));
        v.w = b / (1.f + __expf(-v.w));
        reinterpret_cast<float4*>(out)[i] = v;
    }
}

// ---------------- launch ----------------
extern "C" void kernel_launch(void* const* d_in, const int* in_sizes, int n_in,
                              void* d_out, int out_size) {
    const float* x    = (const float*)d_in[0];
    const int*   idx  = (const int*)d_in[1];
    const float* ea   = (const float*)d_in[2];
    const float* Wx   = (const float*)d_in[3];
    const float* bx   = (const float*)d_in[4];
    const float* We   = (const float*)d_in[5];
    const float* be   = (const float*)d_in[6];
    const float* Wm   = (const float*)d_in[7];
    const float* bm   = (const float*)d_in[8];
    const float* beta = (const float*)d_in[9];

    const int N = in_sizes[0] / 128;
    const int E = in_sizes[2] / 64;
    const int n_tiles_node = (N + 127) / 128;
    const int ngroups = (E + 15) / 16;
    const int n4 = N * OUT / 4;

    prep_kernel<<<194, 128>>>(Wx, bx, We, be, Wm, bm, idx);

    cudaFuncSetAttribute(node_mma_kernel, cudaFuncAttributeMaxDynamicSharedMemorySize,
                         NODE_SMEM);
    node_mma_kernel<<<n_tiles_node, 256, NODE_SMEM>>>(x, N, n_tiles_node, n4);

    cudaFuncSetAttribute(edge_mma_kernel, cudaFuncAttributeMaxDynamicSharedMemorySize,
                         EDGE_SMEM);
    edge_mma_kernel<<<148 * 2, 256, EDGE_SMEM>>>(ea, idx, E, ngroups);

    final_kernel<<<1024, 256>>>((float*)d_out, beta, n4);
}

// round 15
// speedup vs baseline: 1.4646x; 1.0236x over previous
#include <cuda_runtime.h>
#include <cuda_bf16.h>
#include <cstdint>

#define N_MAX   50000
#define OUT     128
#define EDIM    64

// ---------------- device scratch ----------------
__device__ __align__(16) float g_W1[128 * 128];
__device__ __align__(16) float g_W2[64 * 128];    // [k][n] fp32
__device__ __align__(16) float g_c[128];
__device__ __align__(16) float g_A[(size_t)N_MAX * OUT];    // x@W1 + c (bias folded)
__device__ __align__(16) float g_agg[(size_t)N_MAX * OUT];
__device__ int g_is64;

// ---------------- helpers ----------------
__device__ __forceinline__ uint32_t smem_u32(const void* p) {
    uint32_t a;
    asm("{ .reg .u64 t; cvta.to.shared.u64 t, %1; cvt.u32.u64 %0, t; }" : "=r"(a) : "l"(p));
    return a;
}
#define SW128(off) ((off) ^ (((off) >> 3) & 0x70))

__device__ __forceinline__ void ldsm4(uint32_t& r0, uint32_t& r1, uint32_t& r2,
                                      uint32_t& r3, uint32_t a) {
    asm volatile("ldmatrix.sync.aligned.m8n8.x4.shared.b16 {%0,%1,%2,%3}, [%4];"
                 : "=r"(r0), "=r"(r1), "=r"(r2), "=r"(r3) : "r"(a));
}
__device__ __forceinline__ void mma16816(float* c, const uint32_t* a, uint32_t b0,
                                         uint32_t b1) {
    asm volatile(
        "mma.sync.aligned.m16n8k16.row.col.f32.bf16.bf16.f32 "
        "{%0,%1,%2,%3}, {%4,%5,%6,%7}, {%8,%9}, {%0,%1,%2,%3};"
        : "+f"(c[0]), "+f"(c[1]), "+f"(c[2]), "+f"(c[3])
        : "r"(a[0]), "r"(a[1]), "r"(a[2]), "r"(a[3]), "r"(b0), "r"(b1));
}
__device__ __forceinline__ void split2(const float2 v, uint32_t& h, uint32_t& l) {
    asm("cvt.rn.bf16x2.f32 %0, %1, %2;" : "=r"(h) : "f"(v.y), "f"(v.x));
    const float hx = __uint_as_float(h << 16);
    const float hy = __uint_as_float(h & 0xffff0000u);
    asm("cvt.rn.bf16x2.f32 %0, %1, %2;" : "=r"(l) : "f"(v.y - hy), "f"(v.x - hx));
}
__device__ __forceinline__ float lky(float x) { return (x > 0.f) ? x : 0.01f * x; }

// ---------------- fold weights + detect int64 (fused); 256-thread k-split ----------------
// Block b<194, 256 threads: thread j and j+128 compute half k-ranges of column j&127.
__global__ void prep_kernel(const float* __restrict__ Wx, const float* __restrict__ bx,
                            const float* __restrict__ We, const float* __restrict__ be,
                            const float* __restrict__ Wm, const float* __restrict__ bm,
                            const int* __restrict__ idx) {
    __shared__ float row[128];
    __shared__ float row2[128];
    __shared__ float part[256];
    const int b = blockIdx.x;
    const int j = threadIdx.x;          // 0..255
    const int col = j & 127;
    const int half = j >> 7;            // 0 or 1
    if (b == 193) {
        if (j == 0) {
            int ok = 1;
            for (int i = 1; i < 64; i += 2)
                if (idx[i] != 0) ok = 0;
            g_is64 = ok;
        }
        return;
    }
    if (b < 128) {
        if (j < 128) row[j] = Wx[b * 128 + j];
        __syncthreads();
        const int k0 = half * 64;
        float s0 = 0.f, s1 = 0.f;
#pragma unroll 8
        for (int k = 0; k < 32; k++) {
            s0 = fmaf(row[k0 + k],      Wm[(k0 + k) * 128 + col], s0);
            s1 = fmaf(row[k0 + 32 + k], Wm[(k0 + 32 + k) * 128 + col], s1);
        }
        part[j] = s0 + s1;
        __syncthreads();
        if (j < 128) g_W1[b * 128 + j] = part[j] + part[j + 128];
    } else if (b < 192) {
        const int i = b - 128;
        if (j < 128) row[j] = We[i * 128 + j];
        __syncthreads();
        const int k0 = half * 64;
        float s0 = 0.f, s1 = 0.f;
#pragma unroll 8
        for (int k = 0; k < 32; k++) {
            s0 = fmaf(row[k0 + k],      Wm[(128 + k0 + k) * 128 + col], s0);
            s1 = fmaf(row[k0 + 32 + k], Wm[(128 + k0 + 32 + k) * 128 + col], s1);
        }
        part[j] = s0 + s1;
        __syncthreads();
        if (j < 128) g_W2[i * 128 + j] = part[j] + part[j + 128];
    } else {
        if (j < 128) { row[j] = bx[j]; row2[j] = be[j]; }
        __syncthreads();
        // half 0: bx @ Wm[0:128]; half 1: be @ Wm[128:256]
        const float* rp = (half == 0) ? row : row2;
        const int base = half * 128;
        float s0 = 0.f, s1 = 0.f;
#pragma unroll 8
        for (int k = 0; k < 64; k++) {
            s0 = fmaf(rp[k],      Wm[(base + k) * 128 + col], s0);
            s1 = fmaf(rp[k + 64], Wm[(base + k + 64) * 128 + col], s1);
        }
        part[j] = s0 + s1;
        __syncthreads();
        if (j < 128) g_c[j] = bm[j] + part[j] + part[j + 128];
    }
}

// ---------------- node GEMM: direct-LDG A frags, bf16 mma x3, bias folded ----------------
#define NB_HI     0
#define NB_LO     32768
#define NODE_SMEM 65536

__global__ void __launch_bounds__(256, 2) node_mma_kernel(const float* __restrict__ x,
                                                          int N, int ntiles, int n4) {
    extern __shared__ char smem[];
    const uint32_t sb = smem_u32(smem);
    const int tid = threadIdx.x;
    const int wid = tid >> 5;
    const int lane = tid & 31;

    // fused: zero the aggregation buffer
    {
        const float4 z = make_float4(0.f, 0.f, 0.f, 0.f);
        const int stride = gridDim.x * blockDim.x;
        for (int i = blockIdx.x * blockDim.x + tid; i < n4; i += stride)
            reinterpret_cast<float4*>(g_agg)[i] = z;
    }

    for (int i = tid; i < 128 * 128; i += 256) {
        const int k = i >> 7, n = i & 127;
        const float v = g_W1[i];
        const __nv_bfloat16 h = __float2bfloat16(v);
        const __nv_bfloat16 l = __float2bfloat16(v - __bfloat162float(h));
        const uint32_t off = (uint32_t)(n * 2 + (k >> 6)) * 128 + (uint32_t)(k & 63) * 2;
        const uint32_t sw = SW128(off);
        *reinterpret_cast<__nv_bfloat16*>(smem + NB_HI + sw) = h;
        *reinterpret_cast<__nv_bfloat16*>(smem + NB_LO + sw) = l;
    }
    __syncthreads();

    const int qd = lane >> 2;
    const int tq = lane & 3;
    const int b_row = ((lane >= 16) ? 8 : 0) + (lane & 7);
    const int b_kb = ((lane >> 3) & 1) * 16;

    for (int tp = blockIdx.x; tp < ntiles; tp += gridDim.x) {
        const int base_r = tp * 128 + wid * 16;

        const int r_lo = min(base_r + qd, N - 1);
        const int r_hi = min(base_r + qd + 8, N - 1);
        const float* plo = x + (size_t)r_lo * 128 + 2 * tq;
        const float* phi = x + (size_t)r_hi * 128 + 2 * tq;
        uint32_t ah[8][4], al[8][4];
#pragma unroll
        for (int ks = 0; ks < 8; ks++) {
            const float2 v00 = __ldg(reinterpret_cast<const float2*>(plo + ks * 16));
            const float2 v10 = __ldg(reinterpret_cast<const float2*>(phi + ks * 16));
            const float2 v01 = __ldg(reinterpret_cast<const float2*>(plo + ks * 16 + 8));
            const float2 v11 = __ldg(reinterpret_cast<const float2*>(phi + ks * 16 + 8));
            split2(v00, ah[ks][0], al[ks][0]);
            split2(v10, ah[ks][1], al[ks][1]);
            split2(v01, ah[ks][2], al[ks][2]);
            split2(v11, ah[ks][3], al[ks][3]);
        }

#pragma unroll
        for (int jp = 0; jp < 4; jp++) {
            const int j0 = jp * 2, j1 = jp * 2 + 1;
            float p0[4] = {0.f, 0.f, 0.f, 0.f}, p1[4] = {0.f, 0.f, 0.f, 0.f};
            float q0[4] = {0.f, 0.f, 0.f, 0.f}, q1[4] = {0.f, 0.f, 0.f, 0.f};
#pragma unroll
            for (int ks = 0; ks < 8; ks++) {
                const uint32_t base_off = (uint32_t)((ks >> 2) * 128 +
                                                     (ks & 3) * 32 + b_kb);
                const uint32_t sw0 = SW128((uint32_t)((16 * j0 + b_row) * 256) + base_off);
                const uint32_t sw1 = SW128((uint32_t)((16 * j1 + b_row) * 256) + base_off);
                uint32_t bh0, bh1, bh2, bh3, bl0, bl1, bl2, bl3;
                uint32_t ch0, ch1, ch2, ch3, cl0, cl1, cl2, cl3;
                ldsm4(bh0, bh1, bh2, bh3, sb + NB_HI + sw0);
                ldsm4(bl0, bl1, bl2, bl3, sb + NB_LO + sw0);
                ldsm4(ch0, ch1, ch2, ch3, sb + NB_HI + sw1);
                ldsm4(cl0, cl1, cl2, cl3, sb + NB_LO + sw1);
                mma16816(p0, ah[ks], bh0, bh1);
                mma16816(p1, ah[ks], bh2, bh3);
                mma16816(q0, ah[ks], ch0, ch1);
                mma16816(q1, ah[ks], ch2, ch3);
                mma16816(p0, ah[ks], bl0, bl1);
                mma16816(p1, ah[ks], bl2, bl3);
                mma16816(q0, ah[ks], cl0, cl1);
                mma16816(q1, ah[ks], cl2, cl3);
                mma16816(p0, al[ks], bh0, bh1);
                mma16816(p1, al[ks], bh2, bh3);
                mma16816(q0, al[ks], ch0, ch1);
                mma16816(q1, al[ks], ch2, ch3);
            }
            const int r0 = base_r + (lane >> 2);
            const int c0 = 2 * (lane & 3);
            const float2 cj0a = __ldg(reinterpret_cast<const float2*>(g_c + j0 * 16 + c0));
            const float2 cj0b = __ldg(reinterpret_cast<const float2*>(g_c + j0 * 16 + c0 + 8));
            const float2 cj1a = __ldg(reinterpret_cast<const float2*>(g_c + j1 * 16 + c0));
            const float2 cj1b = __ldg(reinterpret_cast<const float2*>(g_c + j1 * 16 + c0 + 8));
            if (r0 < N) {
                float* p = &g_A[(size_t)r0 * 128];
                *reinterpret_cast<float2*>(p + j0 * 16 + c0) =
                    make_float2(p0[0] + cj0a.x, p0[1] + cj0a.y);
                *reinterpret_cast<float2*>(p + j0 * 16 + c0 + 8) =
                    make_float2(p1[0] + cj0b.x, p1[1] + cj0b.y);
                *reinterpret_cast<float2*>(p + j1 * 16 + c0) =
                    make_float2(q0[0] + cj1a.x, q0[1] + cj1a.y);
                *reinterpret_cast<float2*>(p + j1 * 16 + c0 + 8) =
                    make_float2(q1[0] + cj1b.x, q1[1] + cj1b.y);
            }
            if (r0 + 8 < N) {
                float* p = &g_A[(size_t)(r0 + 8) * 128];
                *reinterpret_cast<float2*>(p + j0 * 16 + c0) =
                    make_float2(p0[2] + cj0a.x, p0[3] + cj0a.y);
                *reinterpret_cast<float2*>(p + j0 * 16 + c0 + 8) =
                    make_float2(p1[2] + cj0b.x, p1[3] + cj0b.y);
                *reinterpret_cast<float2*>(p + j1 * 16 + c0) =
                    make_float2(q0[2] + cj1a.x, q0[3] + cj1a.y);
                *reinterpret_cast<float2*>(p + j1 * 16 + c0 + 8) =
                    make_float2(q1[2] + cj1b.x, q1[3] + cj1b.y);
            }
        }
    }
}

// ---------------- edge kernel: R12 structure + cnt==16 fast-path epilogue ----------------
// SMEM: B_hi 16KB | B_lo 16KB | 8 warp D regions [16 x 136 fp32]
#define B_HI_OFF  0
#define B_LO_OFF  16384
#define WARP_D    32768
#define DSTRIDE   136
#define WD_SZ     (16 * DSTRIDE * 4)
#define EDGE_SMEM (32768 + 8 * WD_SZ)

__global__ void __launch_bounds__(256, 2) edge_mma_kernel(const float* __restrict__ ea,
                                                          const int* __restrict__ idx,
                                                          int E, int ngroups) {
    extern __shared__ char smem[];
    const uint32_t sb = smem_u32(smem);
    const int tid = threadIdx.x;
    const int wid = tid >> 5;
    const int lane = tid & 31;
    const int is64 = g_is64;

    // build B tiles (hi/lo split of W2^T)
    for (int i = tid; i < 64 * 128; i += 256) {
        const int k = i >> 7, n = i & 127;
        const float v = g_W2[i];
        const __nv_bfloat16 h = __float2bfloat16(v);
        const __nv_bfloat16 l = __float2bfloat16(v - __bfloat162float(h));
        const uint32_t off = (uint32_t)n * 128 + (uint32_t)k * 2;
        const uint32_t sw = SW128(off);
        *reinterpret_cast<__nv_bfloat16*>(smem + B_HI_OFF + sw) = h;
        *reinterpret_cast<__nv_bfloat16*>(smem + B_LO_OFF + sw) = l;
    }
    __syncthreads();

    float* dbuf = reinterpret_cast<float*>(smem + WARP_D + wid * WD_SZ);

    const int qd = lane >> 2;
    const int tq = lane & 3;
    const int b_row = ((lane >= 16) ? 8 : 0) + (lane & 7);
    const int b_kb = ((lane >> 3) & 1) * 16;

    const int gw = blockIdx.x * 8 + wid;
    const int nwarps = gridDim.x * 8;

    for (int g = gw; g < ngroups; g += nwarps) {
        const long long base_e = (long long)g * 16;

        // ---- A fragments directly from global (hi/lo split in regs) ----
        const long long e_lo = min(base_e + qd, (long long)E - 1);
        const long long e_hi = min(base_e + qd + 8, (long long)E - 1);
        const float* plo = ea + e_lo * 64 + 2 * tq;
        const float* phi = ea + e_hi * 64 + 2 * tq;
        uint32_t ah[4][4], al[4][4];
#pragma unroll
        for (int ks = 0; ks < 4; ks++) {
            const float2 v00 = __ldg(reinterpret_cast<const float2*>(plo + ks * 16));
            const float2 v10 = __ldg(reinterpret_cast<const float2*>(phi + ks * 16));
            const float2 v01 = __ldg(reinterpret_cast<const float2*>(plo + ks * 16 + 8));
            const float2 v11 = __ldg(reinterpret_cast<const float2*>(phi + ks * 16 + 8));
            split2(v00, ah[ks][0], al[ks][0]);
            split2(v10, ah[ks][1], al[ks][1]);
            split2(v01, ah[ks][2], al[ks][2]);
            split2(v11, ah[ks][3], al[ks][3]);
        }

        // ---- edge indices: lane t (<16) holds edge base_e + t ----
        int sidx = 0, didx = 0;
        {
            const long long e = base_e + lane;
            if (lane < 16 && e < E) {
                sidx = idx[is64 ? 2 * e : e];
                didx = idx[is64 ? 2 * (e + E) : (e + E)];
            }
        }

        // ---- compute: 8 n-pairs; SPLIT acc chains (hi-chain + cross-chain) ----
#pragma unroll
        for (int j = 0; j < 8; j++) {
            float a0h[4] = {0.f, 0.f, 0.f, 0.f}, a0x[4] = {0.f, 0.f, 0.f, 0.f};
            float a1h[4] = {0.f, 0.f, 0.f, 0.f}, a1x[4] = {0.f, 0.f, 0.f, 0.f};
#pragma unroll
            for (int ks = 0; ks < 4; ks++) {
                const uint32_t boff =
                    (uint32_t)((16 * j + b_row) * 128 + ks * 32 + b_kb);
                const uint32_t sw = SW128(boff);
                uint32_t bh0, bh1, bh2, bh3, bl0, bl1, bl2, bl3;
                ldsm4(bh0, bh1, bh2, bh3, sb + B_HI_OFF + sw);
                ldsm4(bl0, bl1, bl2, bl3, sb + B_LO_OFF + sw);
                mma16816(a0h, ah[ks], bh0, bh1);      // hi*hi chain (depth 4)
                mma16816(a1h, ah[ks], bh2, bh3);
                mma16816(a0x, ah[ks], bl0, bl1);      // cross chain (depth 8)
                mma16816(a1x, ah[ks], bl2, bl3);
                mma16816(a0x, al[ks], bh0, bh1);
                mma16816(a1x, al[ks], bh2, bh3);
            }
            const int r0 = lane >> 2;
            const int c0 = j * 16 + 2 * (lane & 3);
            *reinterpret_cast<float2*>(dbuf + r0 * DSTRIDE + c0) =
                make_float2(a0h[0] + a0x[0], a0h[1] + a0x[1]);
            *reinterpret_cast<float2*>(dbuf + (r0 + 8) * DSTRIDE + c0) =
                make_float2(a0h[2] + a0x[2], a0h[3] + a0x[3]);
            *reinterpret_cast<float2*>(dbuf + r0 * DSTRIDE + c0 + 8) =
                make_float2(a1h[0] + a1x[0], a1h[1] + a1x[1]);
            *reinterpret_cast<float2*>(dbuf + (r0 + 8) * DSTRIDE + c0 + 8) =
                make_float2(a1h[2] + a1x[2], a1h[3] + a1x[3]);
        }
        __syncwarp();

        // ---- epilogue: coalesced gather (pipelined depth 2) + leaky + v4 RED ----
        const int cnt = (int)min((long long)16, (long long)E - base_e);
        float4 gbuf[2];
        int dd[2];
        {
            const int s0 = __shfl_sync(0xffffffffu, sidx, 0);
            dd[0] = __shfl_sync(0xffffffffu, didx, 0);
            gbuf[0] = __ldg(reinterpret_cast<const float4*>(
                &g_A[(size_t)s0 * 128 + lane * 4]));
            if (cnt > 1) {
                const int s1 = __shfl_sync(0xffffffffu, sidx, 1);
                dd[1] = __shfl_sync(0xffffffffu, didx, 1);
                gbuf[1] = __ldg(reinterpret_cast<const float4*>(
                    &g_A[(size_t)s1 * 128 + lane * 4]));
            }
        }
        if (cnt == 16) {
#pragma unroll 4
            for (int t = 0; t < 16; t++) {
                const float4 av = gbuf[t & 1];
                const int d = dd[t & 1];
                if (t + 2 < 16) {
                    const int sn = __shfl_sync(0xffffffffu, sidx, t + 2);
                    dd[t & 1] = __shfl_sync(0xffffffffu, didx, t + 2);
                    gbuf[t & 1] = __ldg(reinterpret_cast<const float4*>(
                        &g_A[(size_t)sn * 128 + lane * 4]));
                }
                const float4 dv =
                    *reinterpret_cast<const float4*>(dbuf + t * DSTRIDE + lane * 4);
                const float o0 = lky(dv.x + av.x);
                const float o1 = lky(dv.y + av.y);
                const float o2 = lky(dv.z + av.z);
                const float o3 = lky(dv.w + av.w);
                asm volatile("red.global.add.v4.f32 [%0], {%1, %2, %3, %4};" ::
                                 "l"(&g_agg[(size_t)d * 128 + lane * 4]),
                                 "f"(o0), "f"(o1), "f"(o2), "f"(o3)
                             : "memory");
            }
        } else {
            for (int t = 0; t < cnt; t++) {
                const float4 av = gbuf[t & 1];
                const int d = dd[t & 1];
                if (t + 2 < cnt) {
                    const int sn = __shfl_sync(0xffffffffu, sidx, t + 2);
                    dd[t & 1] = __shfl_sync(0xffffffffu, didx, t + 2);
                    gbuf[t & 1] = __ldg(reinterpret_cast<const float4*>(
                        &g_A[(size_t)sn * 128 + lane * 4]));
                }
                const float4 dv =
                    *reinterpret_cast<const float4*>(dbuf + t * DSTRIDE + lane * 4);
                const float o0 = lky(dv.x + av.x);
                const float o1 = lky(dv.y + av.y);
                const float o2 = lky(dv.z + av.z);
                const float o3 = lky(dv.w + av.w);
                asm volatile("red.global.add.v4.f32 [%0], {%1, %2, %3, %4};" ::
                                 "l"(&g_agg[(size_t)d * 128 + lane * 4]),
                                 "f"(o0), "f"(o1), "f"(o2), "f"(o3)
                             : "memory");
            }
        }
        __syncwarp();  // D region reused next group
    }
}

// ---------------- epilogue: out = sigmoid(agg) * relu(beta) ----------------
__global__ void final_kernel(float* __restrict__ out, const float* __restrict__ beta,
                             int n4) {
    float b = beta[0];
    b = (b > 0.f) ? b : 0.f;
    int i = blockIdx.x * blockDim.x + threadIdx.x;
    const int stride = gridDim.x * blockDim.x;
    for (; i < n4; i += stride) {
        float4 v = reinterpret_cast<const float4*>(g_agg)[i];
        v.x = b / (1.f + __expf(-v.x));
        v.y = b / (1.f + __expf(-v.y));
        v.z = b / (1.f + __expf(-v.z));
        v.w = b / (1.f + __expf(-v.w));
        reinterpret_cast<float4*>(out)[i] = v;
    }
}

// ---------------- launch ----------------
extern "C" void kernel_launch(void* const* d_in, const int* in_sizes, int n_in,
                              void* d_out, int out_size) {
    const float* x    = (const float*)d_in[0];
    const int*   idx  = (const int*)d_in[1];
    const float* ea   = (const float*)d_in[2];
    const float* Wx   = (const float*)d_in[3];
    const float* bx   = (const float*)d_in[4];
    const float* We   = (const float*)d_in[5];
    const float* be   = (const float*)d_in[6];
    const float* Wm   = (const float*)d_in[7];
    const float* bm   = (const float*)d_in[8];
    const float* beta = (const float*)d_in[9];

    const int N = in_sizes[0] / 128;
    const int E = in_sizes[2] / 64;
    const int n_tiles_node = (N + 127) / 128;
    const int ngroups = (E + 15) / 16;
    const int n4 = N * OUT / 4;

    prep_kernel<<<194, 256>>>(Wx, bx, We, be, Wm, bm, idx);

    cudaFuncSetAttribute(node_mma_kernel, cudaFuncAttributeMaxDynamicSharedMemorySize,
                         NODE_SMEM);
    node_mma_kernel<<<n_tiles_node, 256, NODE_SMEM>>>(x, N, n_tiles_node, n4);

    cudaFuncSetAttribute(edge_mma_kernel, cudaFuncAttributeMaxDynamicSharedMemorySize,
                         EDGE_SMEM);
    edge_mma_kernel<<<148 * 2, 256, EDGE_SMEM>>>(ea, idx, E, ngroups);

    final_kernel<<<1024, 256>>>((float*)d_out, beta, n4);
}

// round 16
// speedup vs baseline: 1.5365x; 1.0491x over previous
#include <cuda_runtime.h>
#include <cuda_bf16.h>
#include <cstdint>

#define N_MAX   50000
#define OUT     128
#define EDIM    64

// ---------------- device scratch ----------------
__device__ __align__(16) float g_W1[128 * 128];
__device__ __align__(16) float g_W2[64 * 128];    // [k][n] fp32
__device__ __align__(16) float g_c[128];
__device__ __align__(16) float g_A[(size_t)N_MAX * OUT];    // x@W1 + c (bias folded)
__device__ __align__(16) float g_agg[(size_t)N_MAX * OUT];
__device__ int g_is64;

// ---------------- helpers ----------------
__device__ __forceinline__ uint32_t smem_u32(const void* p) {
    uint32_t a;
    asm("{ .reg .u64 t; cvta.to.shared.u64 t, %1; cvt.u32.u64 %0, t; }" : "=r"(a) : "l"(p));
    return a;
}
#define SW128(off) ((off) ^ (((off) >> 3) & 0x70))

__device__ __forceinline__ void ldsm4(uint32_t& r0, uint32_t& r1, uint32_t& r2,
                                      uint32_t& r3, uint32_t a) {
    asm volatile("ldmatrix.sync.aligned.m8n8.x4.shared.b16 {%0,%1,%2,%3}, [%4];"
                 : "=r"(r0), "=r"(r1), "=r"(r2), "=r"(r3) : "r"(a));
}
__device__ __forceinline__ void mma16816(float* c, const uint32_t* a, uint32_t b0,
                                         uint32_t b1) {
    asm volatile(
        "mma.sync.aligned.m16n8k16.row.col.f32.bf16.bf16.f32 "
        "{%0,%1,%2,%3}, {%4,%5,%6,%7}, {%8,%9}, {%0,%1,%2,%3};"
        : "+f"(c[0]), "+f"(c[1]), "+f"(c[2]), "+f"(c[3])
        : "r"(a[0]), "r"(a[1]), "r"(a[2]), "r"(a[3]), "r"(b0), "r"(b1));
}
__device__ __forceinline__ void split2(const float2 v, uint32_t& h, uint32_t& l) {
    asm("cvt.rn.bf16x2.f32 %0, %1, %2;" : "=r"(h) : "f"(v.y), "f"(v.x));
    const float hx = __uint_as_float(h << 16);
    const float hy = __uint_as_float(h & 0xffff0000u);
    asm("cvt.rn.bf16x2.f32 %0, %1, %2;" : "=r"(l) : "f"(v.y - hy), "f"(v.x - hx));
}
__device__ __forceinline__ float lky(float x) { return (x > 0.f) ? x : 0.01f * x; }

// ---------------- fold weights + detect int64 (fused); 256-thread k-split ----------------
__global__ void prep_kernel(const float* __restrict__ Wx, const float* __restrict__ bx,
                            const float* __restrict__ We, const float* __restrict__ be,
                            const float* __restrict__ Wm, const float* __restrict__ bm,
                            const int* __restrict__ idx) {
    __shared__ float row[128];
    __shared__ float row2[128];
    __shared__ float part[256];
    const int b = blockIdx.x;
    const int j = threadIdx.x;          // 0..255
    const int col = j & 127;
    const int half = j >> 7;            // 0 or 1
    if (b == 193) {
        if (j == 0) {
            int ok = 1;
            for (int i = 1; i < 64; i += 2)
                if (idx[i] != 0) ok = 0;
            g_is64 = ok;
        }
        return;
    }
    if (b < 128) {
        if (j < 128) row[j] = Wx[b * 128 + j];
        __syncthreads();
        const int k0 = half * 64;
        float s0 = 0.f, s1 = 0.f;
#pragma unroll 8
        for (int k = 0; k < 32; k++) {
            s0 = fmaf(row[k0 + k],      Wm[(k0 + k) * 128 + col], s0);
            s1 = fmaf(row[k0 + 32 + k], Wm[(k0 + 32 + k) * 128 + col], s1);
        }
        part[j] = s0 + s1;
        __syncthreads();
        if (j < 128) g_W1[b * 128 + j] = part[j] + part[j + 128];
    } else if (b < 192) {
        const int i = b - 128;
        if (j < 128) row[j] = We[i * 128 + j];
        __syncthreads();
        const int k0 = half * 64;
        float s0 = 0.f, s1 = 0.f;
#pragma unroll 8
        for (int k = 0; k < 32; k++) {
            s0 = fmaf(row[k0 + k],      Wm[(128 + k0 + k) * 128 + col], s0);
            s1 = fmaf(row[k0 + 32 + k], Wm[(128 + k0 + 32 + k) * 128 + col], s1);
        }
        part[j] = s0 + s1;
        __syncthreads();
        if (j < 128) g_W2[i * 128 + j] = part[j] + part[j + 128];
    } else {
        if (j < 128) { row[j] = bx[j]; row2[j] = be[j]; }
        __syncthreads();
        const float* rp = (half == 0) ? row : row2;
        const int base = half * 128;
        float s0 = 0.f, s1 = 0.f;
#pragma unroll 8
        for (int k = 0; k < 64; k++) {
            s0 = fmaf(rp[k],      Wm[(base + k) * 128 + col], s0);
            s1 = fmaf(rp[k + 64], Wm[(base + k + 64) * 128 + col], s1);
        }
        part[j] = s0 + s1;
        __syncthreads();
        if (j < 128) g_c[j] = bm[j] + part[j] + part[j + 128];
    }
}

// ---------------- node GEMM: direct-LDG A frags, bf16 mma x3, bias folded ----------------
#define NB_HI     0
#define NB_LO     32768
#define NODE_SMEM 65536

__global__ void __launch_bounds__(256, 2) node_mma_kernel(const float* __restrict__ x,
                                                          int N, int ntiles, int n4) {
    extern __shared__ char smem[];
    const uint32_t sb = smem_u32(smem);
    const int tid = threadIdx.x;
    const int wid = tid >> 5;
    const int lane = tid & 31;

    // fused: zero the aggregation buffer
    {
        const float4 z = make_float4(0.f, 0.f, 0.f, 0.f);
        const int stride = gridDim.x * blockDim.x;
        for (int i = blockIdx.x * blockDim.x + tid; i < n4; i += stride)
            reinterpret_cast<float4*>(g_agg)[i] = z;
    }

    for (int i = tid; i < 128 * 128; i += 256) {
        const int k = i >> 7, n = i & 127;
        const float v = g_W1[i];
        const __nv_bfloat16 h = __float2bfloat16(v);
        const __nv_bfloat16 l = __float2bfloat16(v - __bfloat162float(h));
        const uint32_t off = (uint32_t)(n * 2 + (k >> 6)) * 128 + (uint32_t)(k & 63) * 2;
        const uint32_t sw = SW128(off);
        *reinterpret_cast<__nv_bfloat16*>(smem + NB_HI + sw) = h;
        *reinterpret_cast<__nv_bfloat16*>(smem + NB_LO + sw) = l;
    }
    __syncthreads();

    const int qd = lane >> 2;
    const int tq = lane & 3;
    const int b_row = ((lane >= 16) ? 8 : 0) + (lane & 7);
    const int b_kb = ((lane >> 3) & 1) * 16;

    for (int tp = blockIdx.x; tp < ntiles; tp += gridDim.x) {
        const int base_r = tp * 128 + wid * 16;

        const int r_lo = min(base_r + qd, N - 1);
        const int r_hi = min(base_r + qd + 8, N - 1);
        const float* plo = x + (size_t)r_lo * 128 + 2 * tq;
        const float* phi = x + (size_t)r_hi * 128 + 2 * tq;
        uint32_t ah[8][4], al[8][4];
#pragma unroll
        for (int ks = 0; ks < 8; ks++) {
            const float2 v00 = __ldg(reinterpret_cast<const float2*>(plo + ks * 16));
            const float2 v10 = __ldg(reinterpret_cast<const float2*>(phi + ks * 16));
            const float2 v01 = __ldg(reinterpret_cast<const float2*>(plo + ks * 16 + 8));
            const float2 v11 = __ldg(reinterpret_cast<const float2*>(phi + ks * 16 + 8));
            split2(v00, ah[ks][0], al[ks][0]);
            split2(v10, ah[ks][1], al[ks][1]);
            split2(v01, ah[ks][2], al[ks][2]);
            split2(v11, ah[ks][3], al[ks][3]);
        }

#pragma unroll
        for (int jp = 0; jp < 4; jp++) {
            const int j0 = jp * 2, j1 = jp * 2 + 1;
            float p0[4] = {0.f, 0.f, 0.f, 0.f}, p1[4] = {0.f, 0.f, 0.f, 0.f};
            float q0[4] = {0.f, 0.f, 0.f, 0.f}, q1[4] = {0.f, 0.f, 0.f, 0.f};
#pragma unroll
            for (int ks = 0; ks < 8; ks++) {
                const uint32_t base_off = (uint32_t)((ks >> 2) * 128 +
                                                     (ks & 3) * 32 + b_kb);
                const uint32_t sw0 = SW128((uint32_t)((16 * j0 + b_row) * 256) + base_off);
                const uint32_t sw1 = SW128((uint32_t)((16 * j1 + b_row) * 256) + base_off);
                uint32_t bh0, bh1, bh2, bh3, bl0, bl1, bl2, bl3;
                uint32_t ch0, ch1, ch2, ch3, cl0, cl1, cl2, cl3;
                ldsm4(bh0, bh1, bh2, bh3, sb + NB_HI + sw0);
                ldsm4(bl0, bl1, bl2, bl3, sb + NB_LO + sw0);
                ldsm4(ch0, ch1, ch2, ch3, sb + NB_HI + sw1);
                ldsm4(cl0, cl1, cl2, cl3, sb + NB_LO + sw1);
                mma16816(p0, ah[ks], bh0, bh1);
                mma16816(p1, ah[ks], bh2, bh3);
                mma16816(q0, ah[ks], ch0, ch1);
                mma16816(q1, ah[ks], ch2, ch3);
                mma16816(p0, ah[ks], bl0, bl1);
                mma16816(p1, ah[ks], bl2, bl3);
                mma16816(q0, ah[ks], cl0, cl1);
                mma16816(q1, ah[ks], cl2, cl3);
                mma16816(p0, al[ks], bh0, bh1);
                mma16816(p1, al[ks], bh2, bh3);
                mma16816(q0, al[ks], ch0, ch1);
                mma16816(q1, al[ks], ch2, ch3);
            }
            const int r0 = base_r + (lane >> 2);
            const int c0 = 2 * (lane & 3);
            const float2 cj0a = __ldg(reinterpret_cast<const float2*>(g_c + j0 * 16 + c0));
            const float2 cj0b = __ldg(reinterpret_cast<const float2*>(g_c + j0 * 16 + c0 + 8));
            const float2 cj1a = __ldg(reinterpret_cast<const float2*>(g_c + j1 * 16 + c0));
            const float2 cj1b = __ldg(reinterpret_cast<const float2*>(g_c + j1 * 16 + c0 + 8));
            if (r0 < N) {
                float* p = &g_A[(size_t)r0 * 128];
                *reinterpret_cast<float2*>(p + j0 * 16 + c0) =
                    make_float2(p0[0] + cj0a.x, p0[1] + cj0a.y);
                *reinterpret_cast<float2*>(p + j0 * 16 + c0 + 8) =
                    make_float2(p1[0] + cj0b.x, p1[1] + cj0b.y);
                *reinterpret_cast<float2*>(p + j1 * 16 + c0) =
                    make_float2(q0[0] + cj1a.x, q0[1] + cj1a.y);
                *reinterpret_cast<float2*>(p + j1 * 16 + c0 + 8) =
                    make_float2(q1[0] + cj1b.x, q1[1] + cj1b.y);
            }
            if (r0 + 8 < N) {
                float* p = &g_A[(size_t)(r0 + 8) * 128];
                *reinterpret_cast<float2*>(p + j0 * 16 + c0) =
                    make_float2(p0[2] + cj0a.x, p0[3] + cj0a.y);
                *reinterpret_cast<float2*>(p + j0 * 16 + c0 + 8) =
                    make_float2(p1[2] + cj0b.x, p1[3] + cj0b.y);
                *reinterpret_cast<float2*>(p + j1 * 16 + c0) =
                    make_float2(q0[2] + cj1a.x, q0[3] + cj1a.y);
                *reinterpret_cast<float2*>(p + j1 * 16 + c0 + 8) =
                    make_float2(q1[2] + cj1b.x, q1[3] + cj1b.y);
            }
        }
    }
}

// ---------------- edge kernel: R15 + depth-3 gather pipeline (full unroll, const slots) ----------------
// SMEM: B_hi 16KB | B_lo 16KB | 8 warp D regions [16 x 136 fp32]
#define B_HI_OFF  0
#define B_LO_OFF  16384
#define WARP_D    32768
#define DSTRIDE   136
#define WD_SZ     (16 * DSTRIDE * 4)
#define EDGE_SMEM (32768 + 8 * WD_SZ)

__global__ void __launch_bounds__(256, 2) edge_mma_kernel(const float* __restrict__ ea,
                                                          const int* __restrict__ idx,
                                                          int E, int ngroups) {
    extern __shared__ char smem[];
    const uint32_t sb = smem_u32(smem);
    const int tid = threadIdx.x;
    const int wid = tid >> 5;
    const int lane = tid & 31;
    const int is64 = g_is64;

    // build B tiles (hi/lo split of W2^T)
    for (int i = tid; i < 64 * 128; i += 256) {
        const int k = i >> 7, n = i & 127;
        const float v = g_W2[i];
        const __nv_bfloat16 h = __float2bfloat16(v);
        const __nv_bfloat16 l = __float2bfloat16(v - __bfloat162float(h));
        const uint32_t off = (uint32_t)n * 128 + (uint32_t)k * 2;
        const uint32_t sw = SW128(off);
        *reinterpret_cast<__nv_bfloat16*>(smem + B_HI_OFF + sw) = h;
        *reinterpret_cast<__nv_bfloat16*>(smem + B_LO_OFF + sw) = l;
    }
    __syncthreads();

    float* dbuf = reinterpret_cast<float*>(smem + WARP_D + wid * WD_SZ);

    const int qd = lane >> 2;
    const int tq = lane & 3;
    const int b_row = ((lane >= 16) ? 8 : 0) + (lane & 7);
    const int b_kb = ((lane >> 3) & 1) * 16;

    const int gw = blockIdx.x * 8 + wid;
    const int nwarps = gridDim.x * 8;

    for (int g = gw; g < ngroups; g += nwarps) {
        const long long base_e = (long long)g * 16;

        // ---- A fragments directly from global (hi/lo split in regs) ----
        const long long e_lo = min(base_e + qd, (long long)E - 1);
        const long long e_hi = min(base_e + qd + 8, (long long)E - 1);
        const float* plo = ea + e_lo * 64 + 2 * tq;
        const float* phi = ea + e_hi * 64 + 2 * tq;
        uint32_t ah[4][4], al[4][4];
#pragma unroll
        for (int ks = 0; ks < 4; ks++) {
            const float2 v00 = __ldg(reinterpret_cast<const float2*>(plo + ks * 16));
            const float2 v10 = __ldg(reinterpret_cast<const float2*>(phi + ks * 16));
            const float2 v01 = __ldg(reinterpret_cast<const float2*>(plo + ks * 16 + 8));
            const float2 v11 = __ldg(reinterpret_cast<const float2*>(phi + ks * 16 + 8));
            split2(v00, ah[ks][0], al[ks][0]);
            split2(v10, ah[ks][1], al[ks][1]);
            split2(v01, ah[ks][2], al[ks][2]);
            split2(v11, ah[ks][3], al[ks][3]);
        }

        // ---- edge indices: lane t (<16) holds edge base_e + t ----
        int sidx = 0, didx = 0;
        {
            const long long e = base_e + lane;
            if (lane < 16 && e < E) {
                sidx = idx[is64 ? 2 * e : e];
                didx = idx[is64 ? 2 * (e + E) : (e + E)];
            }
        }

        // ---- compute: 8 n-pairs; SPLIT acc chains (hi-chain + cross-chain) ----
#pragma unroll
        for (int j = 0; j < 8; j++) {
            float a0h[4] = {0.f, 0.f, 0.f, 0.f}, a0x[4] = {0.f, 0.f, 0.f, 0.f};
            float a1h[4] = {0.f, 0.f, 0.f, 0.f}, a1x[4] = {0.f, 0.f, 0.f, 0.f};
#pragma unroll
            for (int ks = 0; ks < 4; ks++) {
                const uint32_t boff =
                    (uint32_t)((16 * j + b_row) * 128 + ks * 32 + b_kb);
                const uint32_t sw = SW128(boff);
                uint32_t bh0, bh1, bh2, bh3, bl0, bl1, bl2, bl3;
                ldsm4(bh0, bh1, bh2, bh3, sb + B_HI_OFF + sw);
                ldsm4(bl0, bl1, bl2, bl3, sb + B_LO_OFF + sw);
                mma16816(a0h, ah[ks], bh0, bh1);      // hi*hi chain (depth 4)
                mma16816(a1h, ah[ks], bh2, bh3);
                mma16816(a0x, ah[ks], bl0, bl1);      // cross chain (depth 8)
                mma16816(a1x, ah[ks], bl2, bl3);
                mma16816(a0x, al[ks], bh0, bh1);
                mma16816(a1x, al[ks], bh2, bh3);
            }
            const int r0 = lane >> 2;
            const int c0 = j * 16 + 2 * (lane & 3);
            *reinterpret_cast<float2*>(dbuf + r0 * DSTRIDE + c0) =
                make_float2(a0h[0] + a0x[0], a0h[1] + a0x[1]);
            *reinterpret_cast<float2*>(dbuf + (r0 + 8) * DSTRIDE + c0) =
                make_float2(a0h[2] + a0x[2], a0h[3] + a0x[3]);
            *reinterpret_cast<float2*>(dbuf + r0 * DSTRIDE + c0 + 8) =
                make_float2(a1h[0] + a1x[0], a1h[1] + a1x[1]);
            *reinterpret_cast<float2*>(dbuf + (r0 + 8) * DSTRIDE + c0 + 8) =
                make_float2(a1h[2] + a1x[2], a1h[3] + a1x[3]);
        }
        __syncwarp();

        // ---- epilogue: coalesced gather + leaky + v4 RED ----
        const int cnt = (int)min((long long)16, (long long)E - base_e);
        if (cnt == 16) {
            // fast path: FULL unroll -> t%3 is compile-time, 3-slot pipe stays in regs
            float4 gbuf[3];
            int dd[3];
#pragma unroll
            for (int p = 0; p < 3; p++) {
                const int sp = __shfl_sync(0xffffffffu, sidx, p);
                dd[p] = __shfl_sync(0xffffffffu, didx, p);
                gbuf[p] = __ldg(reinterpret_cast<const float4*>(
                    &g_A[(size_t)sp * 128 + lane * 4]));
            }
#pragma unroll
            for (int t = 0; t < 16; t++) {
                const int slot = t % 3;
                const float4 av = gbuf[slot];
                const int d = dd[slot];
                if (t + 3 < 16) {
                    const int sn = __shfl_sync(0xffffffffu, sidx, t + 3);
                    dd[slot] = __shfl_sync(0xffffffffu, didx, t + 3);
                    gbuf[slot] = __ldg(reinterpret_cast<const float4*>(
                        &g_A[(size_t)sn * 128 + lane * 4]));
                }
                const float4 dv =
                    *reinterpret_cast<const float4*>(dbuf + t * DSTRIDE + lane * 4);
                const float o0 = lky(dv.x + av.x);
                const float o1 = lky(dv.y + av.y);
                const float o2 = lky(dv.z + av.z);
                const float o3 = lky(dv.w + av.w);
                asm volatile("red.global.add.v4.f32 [%0], {%1, %2, %3, %4};" ::
                                 "l"(&g_agg[(size_t)d * 128 + lane * 4]),
                                 "f"(o0), "f"(o1), "f"(o2), "f"(o3)
                             : "memory");
            }
        } else {
            // slow path: dynamic count, depth-2 (t&1 stays register-resolvable)
            float4 gbuf[2];
            int dd[2];
            {
                const int s0 = __shfl_sync(0xffffffffu, sidx, 0);
                dd[0] = __shfl_sync(0xffffffffu, didx, 0);
                gbuf[0] = __ldg(reinterpret_cast<const float4*>(
                    &g_A[(size_t)s0 * 128 + lane * 4]));
                if (cnt > 1) {
                    const int s1 = __shfl_sync(0xffffffffu, sidx, 1);
                    dd[1] = __shfl_sync(0xffffffffu, didx, 1);
                    gbuf[1] = __ldg(reinterpret_cast<const float4*>(
                        &g_A[(size_t)s1 * 128 + lane * 4]));
                }
            }
            for (int t = 0; t < cnt; t++) {
                const float4 av = gbuf[t & 1];
                const int d = dd[t & 1];
                if (t + 2 < cnt) {
                    const int sn = __shfl_sync(0xffffffffu, sidx, t + 2);
                    dd[t & 1] = __shfl_sync(0xffffffffu, didx, t + 2);
                    gbuf[t & 1] = __ldg(reinterpret_cast<const float4*>(
                        &g_A[(size_t)sn * 128 + lane * 4]));
                }
                const float4 dv =
                    *reinterpret_cast<const float4*>(dbuf + t * DSTRIDE + lane * 4);
                const float o0 = lky(dv.x + av.x);
                const float o1 = lky(dv.y + av.y);
                const float o2 = lky(dv.z + av.z);
                const float o3 = lky(dv.w + av.w);
                asm volatile("red.global.add.v4.f32 [%0], {%1, %2, %3, %4};" ::
                                 "l"(&g_agg[(size_t)d * 128 + lane * 4]),
                                 "f"(o0), "f"(o1), "f"(o2), "f"(o3)
                             : "memory");
            }
        }
        __syncwarp();  // D region reused next group
    }
}

// ---------------- epilogue: out = sigmoid(agg) * relu(beta) ----------------
__global__ void final_kernel(float* __restrict__ out, const float* __restrict__ beta,
                             int n4) {
    float b = beta[0];
    b = (b > 0.f) ? b : 0.f;
    int i = blockIdx.x * blockDim.x + threadIdx.x;
    const int stride = gridDim.x * blockDim.x;
    for (; i < n4; i += stride) {
        float4 v = reinterpret_cast<const float4*>(g_agg)[i];
        v.x = b / (1.f + __expf(-v.x));
        v.y = b / (1.f + __expf(-v.y));
        v.z = b / (1.f + __expf(-v.z));
        v.w = b / (1.f + __expf(-v.w));
        reinterpret_cast<float4*>(out)[i] = v;
    }
}

// ---------------- launch ----------------
extern "C" void kernel_launch(void* const* d_in, const int* in_sizes, int n_in,
                              void* d_out, int out_size) {
    const float* x    = (const float*)d_in[0];
    const int*   idx  = (const int*)d_in[1];
    const float* ea   = (const float*)d_in[2];
    const float* Wx   = (const float*)d_in[3];
    const float* bx   = (const float*)d_in[4];
    const float* We   = (const float*)d_in[5];
    const float* be   = (const float*)d_in[6];
    const float* Wm   = (const float*)d_in[7];
    const float* bm   = (const float*)d_in[8];
    const float* beta = (const float*)d_in[9];

    const int N = in_sizes[0] / 128;
    const int E = in_sizes[2] / 64;
    const int n_tiles_node = (N + 127) / 128;
    const int ngroups = (E + 15) / 16;
    const int n4 = N * OUT / 4;

    prep_kernel<<<194, 256>>>(Wx, bx, We, be, Wm, bm, idx);

    cudaFuncSetAttribute(node_mma_kernel, cudaFuncAttributeMaxDynamicSharedMemorySize,
                         NODE_SMEM);
    node_mma_kernel<<<n_tiles_node, 256, NODE_SMEM>>>(x, N, n_tiles_node, n4);

    cudaFuncSetAttribute(edge_mma_kernel, cudaFuncAttributeMaxDynamicSharedMemorySize,
                         EDGE_SMEM);
    edge_mma_kernel<<<148 * 2, 256, EDGE_SMEM>>>(ea, idx, E, ngroups);

    final_kernel<<<1024, 256>>>((float*)d_out, beta, n4);
}

// round 17
// speedup vs baseline: 1.5386x; 1.0014x over previous
#include <cuda_runtime.h>
#include <cuda_bf16.h>
#include <cstdint>

#define N_MAX   50000
#define OUT     128
#define EDIM    64

// ---------------- device scratch ----------------
__device__ __align__(16) float g_W1[128 * 128];
__device__ __align__(16) float g_W2[64 * 128];    // [k][n] fp32
__device__ __align__(16) float g_c[128];
__device__ __align__(16) float g_A[(size_t)N_MAX * OUT];    // x@W1 + c (bias folded)
__device__ __align__(16) float g_agg[(size_t)N_MAX * OUT];
__device__ int g_is64;

// ---------------- helpers ----------------
__device__ __forceinline__ uint32_t smem_u32(const void* p) {
    uint32_t a;
    asm("{ .reg .u64 t; cvta.to.shared.u64 t, %1; cvt.u32.u64 %0, t; }" : "=r"(a) : "l"(p));
    return a;
}
#define SW128(off) ((off) ^ (((off) >> 3) & 0x70))

__device__ __forceinline__ void ldsm4(uint32_t& r0, uint32_t& r1, uint32_t& r2,
                                      uint32_t& r3, uint32_t a) {
    asm volatile("ldmatrix.sync.aligned.m8n8.x4.shared.b16 {%0,%1,%2,%3}, [%4];"
                 : "=r"(r0), "=r"(r1), "=r"(r2), "=r"(r3) : "r"(a));
}
__device__ __forceinline__ void mma16816(float* c, const uint32_t* a, uint32_t b0,
                                         uint32_t b1) {
    asm volatile(
        "mma.sync.aligned.m16n8k16.row.col.f32.bf16.bf16.f32 "
        "{%0,%1,%2,%3}, {%4,%5,%6,%7}, {%8,%9}, {%0,%1,%2,%3};"
        : "+f"(c[0]), "+f"(c[1]), "+f"(c[2]), "+f"(c[3])
        : "r"(a[0]), "r"(a[1]), "r"(a[2]), "r"(a[3]), "r"(b0), "r"(b1));
}
__device__ __forceinline__ void split2(const float2 v, uint32_t& h, uint32_t& l) {
    asm("cvt.rn.bf16x2.f32 %0, %1, %2;" : "=r"(h) : "f"(v.y), "f"(v.x));
    const float hx = __uint_as_float(h << 16);
    const float hy = __uint_as_float(h & 0xffff0000u);
    asm("cvt.rn.bf16x2.f32 %0, %1, %2;" : "=r"(l) : "f"(v.y - hy), "f"(v.x - hx));
}
__device__ __forceinline__ float lky(float x) { return (x > 0.f) ? x : 0.01f * x; }

// ---------------- fold weights + detect int64 (fused); 256-thread k-split ----------------
__global__ void prep_kernel(const float* __restrict__ Wx, const float* __restrict__ bx,
                            const float* __restrict__ We, const float* __restrict__ be,
                            const float* __restrict__ Wm, const float* __restrict__ bm,
                            const int* __restrict__ idx) {
    __shared__ float row[128];
    __shared__ float row2[128];
    __shared__ float part[256];
    const int b = blockIdx.x;
    const int j = threadIdx.x;          // 0..255
    const int col = j & 127;
    const int half = j >> 7;            // 0 or 1
    if (b == 193) {
        if (j == 0) {
            int ok = 1;
            for (int i = 1; i < 64; i += 2)
                if (idx[i] != 0) ok = 0;
            g_is64 = ok;
        }
        return;
    }
    if (b < 128) {
        if (j < 128) row[j] = Wx[b * 128 + j];
        __syncthreads();
        const int k0 = half * 64;
        float s0 = 0.f, s1 = 0.f;
#pragma unroll 8
        for (int k = 0; k < 32; k++) {
            s0 = fmaf(row[k0 + k],      Wm[(k0 + k) * 128 + col], s0);
            s1 = fmaf(row[k0 + 32 + k], Wm[(k0 + 32 + k) * 128 + col], s1);
        }
        part[j] = s0 + s1;
        __syncthreads();
        if (j < 128) g_W1[b * 128 + j] = part[j] + part[j + 128];
    } else if (b < 192) {
        const int i = b - 128;
        if (j < 128) row[j] = We[i * 128 + j];
        __syncthreads();
        const int k0 = half * 64;
        float s0 = 0.f, s1 = 0.f;
#pragma unroll 8
        for (int k = 0; k < 32; k++) {
            s0 = fmaf(row[k0 + k],      Wm[(128 + k0 + k) * 128 + col], s0);
            s1 = fmaf(row[k0 + 32 + k], Wm[(128 + k0 + 32 + k) * 128 + col], s1);
        }
        part[j] = s0 + s1;
        __syncthreads();
        if (j < 128) g_W2[i * 128 + j] = part[j] + part[j + 128];
    } else {
        if (j < 128) { row[j] = bx[j]; row2[j] = be[j]; }
        __syncthreads();
        const float* rp = (half == 0) ? row : row2;
        const int base = half * 128;
        float s0 = 0.f, s1 = 0.f;
#pragma unroll 8
        for (int k = 0; k < 64; k++) {
            s0 = fmaf(rp[k],      Wm[(base + k) * 128 + col], s0);
            s1 = fmaf(rp[k + 64], Wm[(base + k + 64) * 128 + col], s1);
        }
        part[j] = s0 + s1;
        __syncthreads();
        if (j < 128) g_c[j] = bm[j] + part[j] + part[j + 128];
    }
}

// ---------------- node GEMM: direct-LDG A frags, bf16 mma x3, bias folded ----------------
#define NB_HI     0
#define NB_LO     32768
#define NODE_SMEM 65536

__global__ void __launch_bounds__(256, 2) node_mma_kernel(const float* __restrict__ x,
                                                          int N, int ntiles, int n4) {
    extern __shared__ char smem[];
    const uint32_t sb = smem_u32(smem);
    const int tid = threadIdx.x;
    const int wid = tid >> 5;
    const int lane = tid & 31;

    // fused: zero the aggregation buffer
    {
        const float4 z = make_float4(0.f, 0.f, 0.f, 0.f);
        const int stride = gridDim.x * blockDim.x;
        for (int i = blockIdx.x * blockDim.x + tid; i < n4; i += stride)
            reinterpret_cast<float4*>(g_agg)[i] = z;
    }

    for (int i = tid; i < 128 * 128; i += 256) {
        const int k = i >> 7, n = i & 127;
        const float v = g_W1[i];
        const __nv_bfloat16 h = __float2bfloat16(v);
        const __nv_bfloat16 l = __float2bfloat16(v - __bfloat162float(h));
        const uint32_t off = (uint32_t)(n * 2 + (k >> 6)) * 128 + (uint32_t)(k & 63) * 2;
        const uint32_t sw = SW128(off);
        *reinterpret_cast<__nv_bfloat16*>(smem + NB_HI + sw) = h;
        *reinterpret_cast<__nv_bfloat16*>(smem + NB_LO + sw) = l;
    }
    __syncthreads();

    const int qd = lane >> 2;
    const int tq = lane & 3;
    const int b_row = ((lane >= 16) ? 8 : 0) + (lane & 7);
    const int b_kb = ((lane >> 3) & 1) * 16;

    for (int tp = blockIdx.x; tp < ntiles; tp += gridDim.x) {
        const int base_r = tp * 128 + wid * 16;

        const int r_lo = min(base_r + qd, N - 1);
        const int r_hi = min(base_r + qd + 8, N - 1);
        const float* plo = x + (size_t)r_lo * 128 + 2 * tq;
        const float* phi = x + (size_t)r_hi * 128 + 2 * tq;
        uint32_t ah[8][4], al[8][4];
#pragma unroll
        for (int ks = 0; ks < 8; ks++) {
            const float2 v00 = __ldg(reinterpret_cast<const float2*>(plo + ks * 16));
            const float2 v10 = __ldg(reinterpret_cast<const float2*>(phi + ks * 16));
            const float2 v01 = __ldg(reinterpret_cast<const float2*>(plo + ks * 16 + 8));
            const float2 v11 = __ldg(reinterpret_cast<const float2*>(phi + ks * 16 + 8));
            split2(v00, ah[ks][0], al[ks][0]);
            split2(v10, ah[ks][1], al[ks][1]);
            split2(v01, ah[ks][2], al[ks][2]);
            split2(v11, ah[ks][3], al[ks][3]);
        }

#pragma unroll
        for (int jp = 0; jp < 4; jp++) {
            const int j0 = jp * 2, j1 = jp * 2 + 1;
            float p0[4] = {0.f, 0.f, 0.f, 0.f}, p1[4] = {0.f, 0.f, 0.f, 0.f};
            float q0[4] = {0.f, 0.f, 0.f, 0.f}, q1[4] = {0.f, 0.f, 0.f, 0.f};
#pragma unroll
            for (int ks = 0; ks < 8; ks++) {
                const uint32_t base_off = (uint32_t)((ks >> 2) * 128 +
                                                     (ks & 3) * 32 + b_kb);
                const uint32_t sw0 = SW128((uint32_t)((16 * j0 + b_row) * 256) + base_off);
                const uint32_t sw1 = SW128((uint32_t)((16 * j1 + b_row) * 256) + base_off);
                uint32_t bh0, bh1, bh2, bh3, bl0, bl1, bl2, bl3;
                uint32_t ch0, ch1, ch2, ch3, cl0, cl1, cl2, cl3;
                ldsm4(bh0, bh1, bh2, bh3, sb + NB_HI + sw0);
                ldsm4(bl0, bl1, bl2, bl3, sb + NB_LO + sw0);
                ldsm4(ch0, ch1, ch2, ch3, sb + NB_HI + sw1);
                ldsm4(cl0, cl1, cl2, cl3, sb + NB_LO + sw1);
                mma16816(p0, ah[ks], bh0, bh1);
                mma16816(p1, ah[ks], bh2, bh3);
                mma16816(q0, ah[ks], ch0, ch1);
                mma16816(q1, ah[ks], ch2, ch3);
                mma16816(p0, ah[ks], bl0, bl1);
                mma16816(p1, ah[ks], bl2, bl3);
                mma16816(q0, ah[ks], cl0, cl1);
                mma16816(q1, ah[ks], cl2, cl3);
                mma16816(p0, al[ks], bh0, bh1);
                mma16816(p1, al[ks], bh2, bh3);
                mma16816(q0, al[ks], ch0, ch1);
                mma16816(q1, al[ks], ch2, ch3);
            }
            const int r0 = base_r + (lane >> 2);
            const int c0 = 2 * (lane & 3);
            const float2 cj0a = __ldg(reinterpret_cast<const float2*>(g_c + j0 * 16 + c0));
            const float2 cj0b = __ldg(reinterpret_cast<const float2*>(g_c + j0 * 16 + c0 + 8));
            const float2 cj1a = __ldg(reinterpret_cast<const float2*>(g_c + j1 * 16 + c0));
            const float2 cj1b = __ldg(reinterpret_cast<const float2*>(g_c + j1 * 16 + c0 + 8));
            if (r0 < N) {
                float* p = &g_A[(size_t)r0 * 128];
                *reinterpret_cast<float2*>(p + j0 * 16 + c0) =
                    make_float2(p0[0] + cj0a.x, p0[1] + cj0a.y);
                *reinterpret_cast<float2*>(p + j0 * 16 + c0 + 8) =
                    make_float2(p1[0] + cj0b.x, p1[1] + cj0b.y);
                *reinterpret_cast<float2*>(p + j1 * 16 + c0) =
                    make_float2(q0[0] + cj1a.x, q0[1] + cj1a.y);
                *reinterpret_cast<float2*>(p + j1 * 16 + c0 + 8) =
                    make_float2(q1[0] + cj1b.x, q1[1] + cj1b.y);
            }
            if (r0 + 8 < N) {
                float* p = &g_A[(size_t)(r0 + 8) * 128];
                *reinterpret_cast<float2*>(p + j0 * 16 + c0) =
                    make_float2(p0[2] + cj0a.x, p0[3] + cj0a.y);
                *reinterpret_cast<float2*>(p + j0 * 16 + c0 + 8) =
                    make_float2(p1[2] + cj0b.x, p1[3] + cj0b.y);
                *reinterpret_cast<float2*>(p + j1 * 16 + c0) =
                    make_float2(q0[2] + cj1a.x, q0[3] + cj1a.y);
                *reinterpret_cast<float2*>(p + j1 * 16 + c0 + 8) =
                    make_float2(q1[2] + cj1b.x, q1[3] + cj1b.y);
            }
        }
    }
}

// ---------------- edge kernel: depth-4 gather pipeline (full unroll, t&3 slots) ----------------
// SMEM: B_hi 16KB | B_lo 16KB | 8 warp D regions [16 x 136 fp32]
#define B_HI_OFF  0
#define B_LO_OFF  16384
#define WARP_D    32768
#define DSTRIDE   136
#define WD_SZ     (16 * DSTRIDE * 4)
#define EDGE_SMEM (32768 + 8 * WD_SZ)

__global__ void __launch_bounds__(256, 2) edge_mma_kernel(const float* __restrict__ ea,
                                                          const int* __restrict__ idx,
                                                          int E, int ngroups) {
    extern __shared__ char smem[];
    const uint32_t sb = smem_u32(smem);
    const int tid = threadIdx.x;
    const int wid = tid >> 5;
    const int lane = tid & 31;
    const int is64 = g_is64;

    // build B tiles (hi/lo split of W2^T)
    for (int i = tid; i < 64 * 128; i += 256) {
        const int k = i >> 7, n = i & 127;
        const float v = g_W2[i];
        const __nv_bfloat16 h = __float2bfloat16(v);
        const __nv_bfloat16 l = __float2bfloat16(v - __bfloat162float(h));
        const uint32_t off = (uint32_t)n * 128 + (uint32_t)k * 2;
        const uint32_t sw = SW128(off);
        *reinterpret_cast<__nv_bfloat16*>(smem + B_HI_OFF + sw) = h;
        *reinterpret_cast<__nv_bfloat16*>(smem + B_LO_OFF + sw) = l;
    }
    __syncthreads();

    float* dbuf = reinterpret_cast<float*>(smem + WARP_D + wid * WD_SZ);

    const int qd = lane >> 2;
    const int tq = lane & 3;
    const int b_row = ((lane >= 16) ? 8 : 0) + (lane & 7);
    const int b_kb = ((lane >> 3) & 1) * 16;
    const float* Abase = g_A + lane * 4;       // lane-fixed column offset
    float* aggbase = g_agg + lane * 4;

    const int gw = blockIdx.x * 8 + wid;
    const int nwarps = gridDim.x * 8;

    for (int g = gw; g < ngroups; g += nwarps) {
        const long long base_e = (long long)g * 16;

        // ---- A fragments directly from global (hi/lo split in regs) ----
        const long long e_lo = min(base_e + qd, (long long)E - 1);
        const long long e_hi = min(base_e + qd + 8, (long long)E - 1);
        const float* plo = ea + e_lo * 64 + 2 * tq;
        const float* phi = ea + e_hi * 64 + 2 * tq;
        uint32_t ah[4][4], al[4][4];
#pragma unroll
        for (int ks = 0; ks < 4; ks++) {
            const float2 v00 = __ldg(reinterpret_cast<const float2*>(plo + ks * 16));
            const float2 v10 = __ldg(reinterpret_cast<const float2*>(phi + ks * 16));
            const float2 v01 = __ldg(reinterpret_cast<const float2*>(plo + ks * 16 + 8));
            const float2 v11 = __ldg(reinterpret_cast<const float2*>(phi + ks * 16 + 8));
            split2(v00, ah[ks][0], al[ks][0]);
            split2(v10, ah[ks][1], al[ks][1]);
            split2(v01, ah[ks][2], al[ks][2]);
            split2(v11, ah[ks][3], al[ks][3]);
        }

        // ---- edge indices: lane t (<16) holds edge base_e + t ----
        int sidx = 0, didx = 0;
        {
            const long long e = base_e + lane;
            if (lane < 16 && e < E) {
                sidx = idx[is64 ? 2 * e : e];
                didx = idx[is64 ? 2 * (e + E) : (e + E)];
            }
        }

        // ---- compute: 8 n-pairs; SPLIT acc chains (hi-chain + cross-chain) ----
#pragma unroll
        for (int j = 0; j < 8; j++) {
            float a0h[4] = {0.f, 0.f, 0.f, 0.f}, a0x[4] = {0.f, 0.f, 0.f, 0.f};
            float a1h[4] = {0.f, 0.f, 0.f, 0.f}, a1x[4] = {0.f, 0.f, 0.f, 0.f};
#pragma unroll
            for (int ks = 0; ks < 4; ks++) {
                const uint32_t boff =
                    (uint32_t)((16 * j + b_row) * 128 + ks * 32 + b_kb);
                const uint32_t sw = SW128(boff);
                uint32_t bh0, bh1, bh2, bh3, bl0, bl1, bl2, bl3;
                ldsm4(bh0, bh1, bh2, bh3, sb + B_HI_OFF + sw);
                ldsm4(bl0, bl1, bl2, bl3, sb + B_LO_OFF + sw);
                mma16816(a0h, ah[ks], bh0, bh1);      // hi*hi chain (depth 4)
                mma16816(a1h, ah[ks], bh2, bh3);
                mma16816(a0x, ah[ks], bl0, bl1);      // cross chain (depth 8)
                mma16816(a1x, ah[ks], bl2, bl3);
                mma16816(a0x, al[ks], bh0, bh1);
                mma16816(a1x, al[ks], bh2, bh3);
            }
            const int r0 = lane >> 2;
            const int c0 = j * 16 + 2 * (lane & 3);
            *reinterpret_cast<float2*>(dbuf + r0 * DSTRIDE + c0) =
                make_float2(a0h[0] + a0x[0], a0h[1] + a0x[1]);
            *reinterpret_cast<float2*>(dbuf + (r0 + 8) * DSTRIDE + c0) =
                make_float2(a0h[2] + a0x[2], a0h[3] + a0x[3]);
            *reinterpret_cast<float2*>(dbuf + r0 * DSTRIDE + c0 + 8) =
                make_float2(a1h[0] + a1x[0], a1h[1] + a1x[1]);
            *reinterpret_cast<float2*>(dbuf + (r0 + 8) * DSTRIDE + c0 + 8) =
                make_float2(a1h[2] + a1x[2], a1h[3] + a1x[3]);
        }
        __syncwarp();

        // ---- epilogue: coalesced gather + leaky + v4 RED ----
        const int cnt = (int)min((long long)16, (long long)E - base_e);
        if (cnt == 16) {
            // fast path: FULL unroll, depth-4 pipeline, t&3 slots stay in regs
            float4 gbuf[4];
            int dd[4];
#pragma unroll
            for (int p = 0; p < 4; p++) {
                const int sp = __shfl_sync(0xffffffffu, sidx, p);
                dd[p] = __shfl_sync(0xffffffffu, didx, p);
                gbuf[p] = __ldg(reinterpret_cast<const float4*>(
                    Abase + (size_t)sp * 128));
            }
#pragma unroll
            for (int t = 0; t < 16; t++) {
                const int slot = t & 3;
                const float4 av = gbuf[slot];
                const int d = dd[slot];
                if (t + 4 < 16) {
                    const int sn = __shfl_sync(0xffffffffu, sidx, t + 4);
                    dd[slot] = __shfl_sync(0xffffffffu, didx, t + 4);
                    gbuf[slot] = __ldg(reinterpret_cast<const float4*>(
                        Abase + (size_t)sn * 128));
                }
                const float4 dv =
                    *reinterpret_cast<const float4*>(dbuf + t * DSTRIDE + lane * 4);
                const float o0 = lky(dv.x + av.x);
                const float o1 = lky(dv.y + av.y);
                const float o2 = lky(dv.z + av.z);
                const float o3 = lky(dv.w + av.w);
                asm volatile("red.global.add.v4.f32 [%0], {%1, %2, %3, %4};" ::
                                 "l"(aggbase + (size_t)d * 128),
                                 "f"(o0), "f"(o1), "f"(o2), "f"(o3)
                             : "memory");
            }
        } else {
            // slow path: dynamic count, depth-2 (t&1 stays register-resolvable)
            float4 gbuf[2];
            int dd[2];
            {
                const int s0 = __shfl_sync(0xffffffffu, sidx, 0);
                dd[0] = __shfl_sync(0xffffffffu, didx, 0);
                gbuf[0] = __ldg(reinterpret_cast<const float4*>(
                    Abase + (size_t)s0 * 128));
                if (cnt > 1) {
                    const int s1 = __shfl_sync(0xffffffffu, sidx, 1);
                    dd[1] = __shfl_sync(0xffffffffu, didx, 1);
                    gbuf[1] = __ldg(reinterpret_cast<const float4*>(
                        Abase + (size_t)s1 * 128));
                }
            }
            for (int t = 0; t < cnt; t++) {
                const float4 av = gbuf[t & 1];
                const int d = dd[t & 1];
                if (t + 2 < cnt) {
                    const int sn = __shfl_sync(0xffffffffu, sidx, t + 2);
                    dd[t & 1] = __shfl_sync(0xffffffffu, didx, t + 2);
                    gbuf[t & 1] = __ldg(reinterpret_cast<const float4*>(
                        Abase + (size_t)sn * 128));
                }
                const float4 dv =
                    *reinterpret_cast<const float4*>(dbuf + t * DSTRIDE + lane * 4);
                const float o0 = lky(dv.x + av.x);
                const float o1 = lky(dv.y + av.y);
                const float o2 = lky(dv.z + av.z);
                const float o3 = lky(dv.w + av.w);
                asm volatile("red.global.add.v4.f32 [%0], {%1, %2, %3, %4};" ::
                                 "l"(aggbase + (size_t)d * 128),
                                 "f"(o0), "f"(o1), "f"(o2), "f"(o3)
                             : "memory");
            }
        }
        __syncwarp();  // D region reused next group
    }
}

// ---------------- epilogue: out = sigmoid(agg) * relu(beta) ----------------
__global__ void final_kernel(float* __restrict__ out, const float* __restrict__ beta,
                             int n4) {
    float b = beta[0];
    b = (b > 0.f) ? b : 0.f;
    int i = blockIdx.x * blockDim.x + threadIdx.x;
    const int stride = gridDim.x * blockDim.x;
    for (; i < n4; i += stride) {
        float4 v = reinterpret_cast<const float4*>(g_agg)[i];
        v.x = b / (1.f + __expf(-v.x));
        v.y = b / (1.f + __expf(-v.y));
        v.z = b / (1.f + __expf(-v.z));
        v.w = b / (1.f + __expf(-v.w));
        reinterpret_cast<float4*>(out)[i] = v;
    }
}

// ---------------- launch ----------------
extern "C" void kernel_launch(void* const* d_in, const int* in_sizes, int n_in,
                              void* d_out, int out_size) {
    const float* x    = (const float*)d_in[0];
    const int*   idx  = (const int*)d_in[1];
    const float* ea   = (const float*)d_in[2];
    const float* Wx   = (const float*)d_in[3];
    const float* bx   = (const float*)d_in[4];
    const float* We   = (const float*)d_in[5];
    const float* be   = (const float*)d_in[6];
    const float* Wm   = (const float*)d_in[7];
    const float* bm   = (const float*)d_in[8];
    const float* beta = (const float*)d_in[9];

    const int N = in_sizes[0] / 128;
    const int E = in_sizes[2] / 64;
    const int n_tiles_node = (N + 127) / 128;
    const int ngroups = (E + 15) / 16;
    const int n4 = N * OUT / 4;

    prep_kernel<<<194, 256>>>(Wx, bx, We, be, Wm, bm, idx);

    cudaFuncSetAttribute(node_mma_kernel, cudaFuncAttributeMaxDynamicSharedMemorySize,
                         NODE_SMEM);
    node_mma_kernel<<<n_tiles_node, 256, NODE_SMEM>>>(x, N, n_tiles_node, n4);

    cudaFuncSetAttribute(edge_mma_kernel, cudaFuncAttributeMaxDynamicSharedMemorySize,
                         EDGE_SMEM);
    edge_mma_kernel<<<148 * 2, 256, EDGE_SMEM>>>(ea, idx, E, ngroups);

    final_kernel<<<2048, 256>>>((float*)d_out, beta, n4);
}